// round 12
// baseline (speedup 1.0000x reference)
#include <cuda_runtime.h>
#include <cuda_bf16.h>
#include <math.h>
#include <stdint.h>

#define BATCH 8
#define SEQ   512
#define DMODEL 1024
#define NHEAD 16
#define DHEAD 64
#define MROWS (BATCH*SEQ)        // 4096

// ---------------- scratch (no cudaMalloc allowed) ----------------
__device__ __nv_bfloat16 g_Qh[(size_t)MROWS * 4 * DMODEL];  // qkv hi (32MB)
__device__ __nv_bfloat16 g_Ql[(size_t)MROWS * 4 * DMODEL];  // qkv lo (32MB)
__device__ __nv_bfloat16 g_Ah[(size_t)MROWS * DMODEL];      // x split hi / att hi
__device__ __nv_bfloat16 g_Al[(size_t)MROWS * DMODEL];      // x split lo / att lo
__device__ __nv_bfloat16 g_Bh[(size_t)MROWS * DMODEL];      // Wqkv split hi
__device__ __nv_bfloat16 g_Bl[(size_t)MROWS * DMODEL];      // Wqkv split lo
__device__ __nv_bfloat16 g_Wh[(size_t)DMODEL * DMODEL];     // fc_w split hi
__device__ __nv_bfloat16 g_Wl[(size_t)DMODEL * DMODEL];     // fc_w split lo

// ---------------------------------------------------------------------------
__device__ __forceinline__ uint32_t pkbf2(float a, float b) {
    __nv_bfloat162 t = __floats2bfloat162_rn(a, b);
    return *reinterpret_cast<uint32_t*>(&t);
}

#define N_A4 (MROWS * DMODEL / 4)
#define N_W4 (DMODEL * DMODEL / 4)
__global__ void split3(const float4* __restrict__ x, const float4* __restrict__ wqkv,
                       const float4* __restrict__ fcw)
{
    int i = blockIdx.x * blockDim.x + threadIdx.x;
    const float4* src;
    uint2 *hi, *lo;
    int j;
    if (i < N_A4) {
        src = x;    hi = (uint2*)g_Ah; lo = (uint2*)g_Al; j = i;
    } else if (i < 2 * N_A4) {
        src = wqkv; hi = (uint2*)g_Bh; lo = (uint2*)g_Bl; j = i - N_A4;
    } else if (i < 2 * N_A4 + N_W4) {
        src = fcw;  hi = (uint2*)g_Wh; lo = (uint2*)g_Wl; j = i - 2 * N_A4;
    } else return;

    float4 v = src[j];
    float h0 = __bfloat162float(__float2bfloat16(v.x));
    float h1 = __bfloat162float(__float2bfloat16(v.y));
    float h2 = __bfloat162float(__float2bfloat16(v.z));
    float h3 = __bfloat162float(__float2bfloat16(v.w));
    uint2 H, L;
    H.x = pkbf2(v.x, v.y);           H.y = pkbf2(v.z, v.w);
    L.x = pkbf2(v.x - h0, v.y - h1); L.y = pkbf2(v.z - h2, v.w - h3);
    hi[j] = H;
    lo[j] = L;
}

// ---------------------------------------------------------------------------
#define LDSM4(R0,R1,R2,R3,addr) \
    asm volatile("ldmatrix.sync.aligned.m8n8.x4.shared.b16 {%0,%1,%2,%3}, [%4];" \
        : "=r"(R0),"=r"(R1),"=r"(R2),"=r"(R3) : "r"(addr))
#define LDSM4T(R0,R1,R2,R3,addr) \
    asm volatile("ldmatrix.sync.aligned.m8n8.x4.trans.shared.b16 {%0,%1,%2,%3}, [%4];" \
        : "=r"(R0),"=r"(R1),"=r"(R2),"=r"(R3) : "r"(addr))
#define CPASYNC16(dst, src) \
    asm volatile("cp.async.cg.shared.global [%0], [%1], 16;" :: "r"(dst), "l"(src))
#define CPCOMMIT() asm volatile("cp.async.commit_group;")
#define CPWAIT(n)  asm volatile("cp.async.wait_group %0;" :: "n"(n))

__device__ __forceinline__ void mma16816(float* c, const uint32_t* a,
                                         uint32_t b0, uint32_t b1)
{
    asm volatile(
        "mma.sync.aligned.m16n8k16.row.col.f32.bf16.bf16.f32 "
        "{%0,%1,%2,%3}, {%4,%5,%6,%7}, {%8,%9}, {%0,%1,%2,%3};"
        : "+f"(c[0]), "+f"(c[1]), "+f"(c[2]), "+f"(c[3])
        : "r"(a[0]), "r"(a[1]), "r"(a[2]), "r"(a[3]), "r"(b0), "r"(b1));
}

__device__ __forceinline__ uint32_t sw128(uint32_t off) {
    return off ^ ((off >> 3) & 0x70);
}
__device__ __forceinline__ uint32_t sw64(uint32_t off) {
    return off ^ ((off >> 3) & 0x30);
}

// ---------------------------------------------------------------------------
// HMMA bf16-split GEMM (NT): CTA 64x128, 128 threads (warp 32x64), BK=32,
// 4-stage cp.async ring (one __syncthreads per chunk, 3-deep prefetch),
// 2 CTAs/SM.  Stage: Ah 4K | Al 4K | Bh 8K | Bl 8K = 24KB, rows 64B SW64.
// ---------------------------------------------------------------------------
#define G_AH 0
#define G_AL 4096
#define G_BH 8192
#define G_BL 16384
#define G_STAGE 24576

template<bool SPLIT>
__global__ __launch_bounds__(128, 2)
void gemm_hmma(const __nv_bfloat16* __restrict__ Ah, const __nv_bfloat16* __restrict__ Al,
               const __nv_bfloat16* __restrict__ Bh, const __nv_bfloat16* __restrict__ Bl,
               const float* __restrict__ bias, float* __restrict__ C,
               __nv_bfloat16* __restrict__ Ch, __nv_bfloat16* __restrict__ Cl,
               int N, int K)
{
    extern __shared__ __align__(1024) char smem[];   // 4 x 24KB ring
    const int tid  = threadIdx.x;
    const int wid  = tid >> 5;
    const int lane = tid & 31;
    const int bm   = blockIdx.y * 64;
    const int bn   = blockIdx.x * 128;
    const int wm   = (wid & 1) * 32;
    const int wn   = (wid >> 1) * 64;

    const uint32_t smem_u = (uint32_t)__cvta_generic_to_shared(smem);

    float acc[2][8][4];
#pragma unroll
    for (int i = 0; i < 2; i++)
#pragma unroll
        for (int j = 0; j < 8; j++)
#pragma unroll
            for (int q = 0; q < 4; q++) acc[i][j][q] = 0.f;

    auto load_chunk = [&](int stage, int kc) {
        const int k0 = kc * 32;
        const uint32_t base = smem_u + stage * G_STAGE;
        // A tiles: 64 rows x 32 bf16 (4 x 16B slots/row, 256 slots)
#pragma unroll
        for (int j = 0; j < 2; j++) {
            const int slot = j * 128 + tid;
            const int row = slot >> 2, sl = slot & 3;
            uint32_t off = sw64((uint32_t)(row * 64 + sl * 16));
            CPASYNC16(base + G_AH + off, Ah + (size_t)(bm + row) * K + k0 + sl * 8);
            CPASYNC16(base + G_AL + off, Al + (size_t)(bm + row) * K + k0 + sl * 8);
        }
        // B tiles: 128 rows (512 slots)
#pragma unroll
        for (int j = 0; j < 4; j++) {
            const int slot = j * 128 + tid;
            const int row = slot >> 2, sl = slot & 3;
            uint32_t off = sw64((uint32_t)(row * 64 + sl * 16));
            CPASYNC16(base + G_BH + off, Bh + (size_t)(bn + row) * K + k0 + sl * 8);
            CPASYNC16(base + G_BL + off, Bl + (size_t)(bn + row) * K + k0 + sl * 8);
        }
        CPCOMMIT();
    };

    const int NC = K / 32;          // 32
    load_chunk(0, 0);
    load_chunk(1, 1);
    load_chunk(2, 2);

    const int lrow = lane & 15;
    const int lhi  = lane >> 4;

    for (int c = 0; c < NC; c++) {
        if (c < NC - 2)      { CPWAIT(2); }
        else if (c == NC - 2){ CPWAIT(1); }
        else                 { CPWAIT(0); }
        __syncthreads();             // group c ready + all warps done with stage (c-1)&3
        const uint32_t b = smem_u + (c & 3) * G_STAGE;

#pragma unroll
        for (int ks = 0; ks < 2; ks++) {
            uint32_t ah[2][4], al[2][4];
#pragma unroll
            for (int mi = 0; mi < 2; mi++) {
                const int row = wm + mi * 16 + lrow;
                uint32_t off = sw64((uint32_t)(row * 64 + (ks * 2 + lhi) * 16));
                LDSM4(ah[mi][0], ah[mi][1], ah[mi][2], ah[mi][3], b + G_AH + off);
                LDSM4(al[mi][0], al[mi][1], al[mi][2], al[mi][3], b + G_AL + off);
            }
#pragma unroll
            for (int np = 0; np < 4; np++) {
                uint32_t bh[4], bl[4];
                const int row = wn + np * 16 + lrow;
                uint32_t off = sw64((uint32_t)(row * 64 + (ks * 2 + lhi) * 16));
                LDSM4(bh[0], bh[1], bh[2], bh[3], b + G_BH + off);
                LDSM4(bl[0], bl[1], bl[2], bl[3], b + G_BL + off);
#pragma unroll
                for (int mi = 0; mi < 2; mi++)
#pragma unroll
                    for (int hf = 0; hf < 2; hf++) {
                        const int nj = np * 2 + hf;
                        mma16816(acc[mi][nj], ah[mi], bh[hf], bh[2 + hf]);
                        mma16816(acc[mi][nj], ah[mi], bl[hf], bl[2 + hf]);
                        mma16816(acc[mi][nj], al[mi], bh[hf], bh[2 + hf]);
                    }
            }
        }
        // no second barrier: stage (c+3)&3 == (c-1)&3, drained by the top barrier
        if (c + 3 < NC) load_chunk((c + 3) & 3, c + 3);
    }

#pragma unroll
    for (int mi = 0; mi < 2; mi++) {
        const int m0 = bm + wm + mi * 16 + (lane >> 2);
#pragma unroll
        for (int nj = 0; nj < 8; nj++) {
            const int n0 = bn + wn + nj * 8 + (lane & 3) * 2;
#pragma unroll
            for (int hh = 0; hh < 2; hh++) {
                const int m = m0 + hh * 8;
                float v0 = acc[mi][nj][hh * 2 + 0];
                float v1 = acc[mi][nj][hh * 2 + 1];
                if (SPLIT) {
                    float h0 = __bfloat162float(__float2bfloat16(v0));
                    float h1 = __bfloat162float(__float2bfloat16(v1));
                    *(uint32_t*)(Ch + (size_t)m * N + n0) = pkbf2(v0, v1);
                    *(uint32_t*)(Cl + (size_t)m * N + n0) = pkbf2(v0 - h0, v1 - h1);
                } else {
                    float2 v;
                    v.x = v0 + bias[n0];
                    v.y = v1 + bias[n0 + 1];
                    *(float2*)(C + (size_t)m * N + n0) = v;
                }
            }
        }
    }
}

// ---------------------------------------------------------------------------
// Flash-style HMMA attention, 64-key-chunk softmax (exact R10 best version).
// ---------------------------------------------------------------------------
#define A_OFF_KV 16384
#define A_OFF_KM 114688
#define A_OFF_MK 115200
#define A_SMEM   115712

__global__ __launch_bounds__(128, 2)
void attn_flash(const int* __restrict__ mask, const int* __restrict__ qmask,
                const float* __restrict__ shiftp, const float* __restrict__ biasp)
{
    extern __shared__ __align__(1024) char sm8[];
    const int tid  = threadIdx.x;
    const int lane = tid & 31;
    const int w    = tid >> 5;
    const int qt = blockIdx.x, h = blockIdx.y, b = blockIdx.z;
    const int lrow = lane & 15, lhi = lane >> 4;
    const int g = lane >> 2, t4 = lane & 3;

    const uint32_t su  = (uint32_t)__cvta_generic_to_shared(sm8);
    const uint32_t uKV = su + A_OFF_KV;
    char* sKm8 = sm8 + A_OFF_KM;
    char* sMk8 = sm8 + A_OFF_MK;

    const float shiftv = shiftp[0];
    const float biasv  = biasp[0];
    const size_t rowb  = (size_t)b * SEQ;

    for (int i = tid; i < 512; i += 128) {
        sKm8[i] = (char)qmask[rowb + i];
        sMk8[i] = (char)mask [rowb + i];
    }

#pragma unroll
    for (int t = 0; t < 2; t++) {
        const __nv_bfloat16* src = t ? g_Ql : g_Qh;
#pragma unroll
        for (int j = 0; j < 4; j++) {
            const int slot = j * 128 + tid;
            const int row = slot >> 3, sl = slot & 7;
            CPASYNC16(su + t * 8192 + sw128((uint32_t)(row * 128 + sl * 16)),
                      src + (rowb + qt * 64 + row) * 4096 + h * 64 + sl * 8);
        }
    }
    CPCOMMIT();

    auto ldKV = [&](int buf, int kt) {
        const uint32_t base = uKV + buf * 49152;
#pragma unroll
        for (int t = 0; t < 4; t++) {
            const __nv_bfloat16* src = (t & 1) ? g_Ql : g_Qh;
            const int colb = ((t >> 1) ? 2048 : 1024) + h * 64;
#pragma unroll
            for (int j = 0; j < 4; j++) {
                const int slot = j * 128 + tid;
                const int row = slot >> 3, sl = slot & 7;
                CPASYNC16(base + t * 8192 + sw128((uint32_t)(row * 128 + sl * 16)),
                          src + (rowb + kt * 64 + row) * 4096 + colb + sl * 8);
            }
        }
#pragma unroll
        for (int t = 0; t < 2; t++) {
            const __nv_bfloat16* src = t ? g_Ql : g_Qh;
#pragma unroll
            for (int j = 0; j < 4; j++) {
                const int slot = j * 128 + tid;
                const int row = slot >> 3, sl = slot & 7;
                CPASYNC16(base + 32768 + t * 8192 + sw128((uint32_t)(row * 128 + sl * 16)),
                          src + (rowb + kt * 64 + row) * 4096 + 3072 + h * 64 + sl * 8);
            }
        }
        CPCOMMIT();
    };

    ldKV(0, 0);
    ldKV(1, 1);

    CPWAIT(2);                  // Q landed
    __syncthreads();

    uint32_t qh[4][4], ql[4][4];
#pragma unroll
    for (int ks = 0; ks < 4; ks++) {
        uint32_t off = sw128((uint32_t)((w * 16 + lrow) * 128 + (ks * 2 + lhi) * 16));
        LDSM4(qh[ks][0], qh[ks][1], qh[ks][2], qh[ks][3], su + off);
        LDSM4(ql[ks][0], ql[ks][1], ql[ks][2], ql[ks][3], su + 8192 + off);
    }

    char  qmv[2];
    float qgf[2];
#pragma unroll
    for (int hf = 0; hf < 2; hf++) {
        const int qr = qt * 64 + w * 16 + g + hf * 8;
        qmv[hf] = sKm8[qr];
        qgf[hf] = (float)qr;
    }

    float o[8][4];
#pragma unroll
    for (int d = 0; d < 8; d++)
#pragma unroll
        for (int q = 0; q < 4; q++) o[d][q] = 0.f;
    float mx[2] = {-1e30f, -1e30f};
    float sum[2] = {0.f, 0.f};

    for (int kt = 0; kt < 8; kt++) {
        if (kt == 7) { CPWAIT(0); } else { CPWAIT(1); }
        __syncthreads();
        const uint32_t kb = uKV + (kt & 1) * 49152;

        // ---- phase 1: scores for all 64 keys of this chunk ----
        float sv[4][2][2][2];               // [kp][nf][e][hf]
        float cmax[2] = {-1e30f, -1e30f};
#pragma unroll
        for (int kp = 0; kp < 4; kp++) {
            float a1[2][4], a2[2][4];
#pragma unroll
            for (int nf = 0; nf < 2; nf++)
#pragma unroll
                for (int q = 0; q < 4; q++) { a1[nf][q] = 0.f; a2[nf][q] = 0.f; }

#pragma unroll
            for (int ks = 0; ks < 4; ks++) {
                uint32_t k1h[4], k1l[4], k2h[4], k2l[4];
                uint32_t off = sw128((uint32_t)((kp * 16 + lrow) * 128 + (ks * 2 + lhi) * 16));
                LDSM4(k1h[0], k1h[1], k1h[2], k1h[3], kb + off);
                LDSM4(k1l[0], k1l[1], k1l[2], k1l[3], kb + 8192 + off);
                LDSM4(k2h[0], k2h[1], k2h[2], k2h[3], kb + 16384 + off);
                LDSM4(k2l[0], k2l[1], k2l[2], k2l[3], kb + 24576 + off);
#pragma unroll
                for (int nf = 0; nf < 2; nf++) {
                    mma16816(a1[nf], qh[ks], k1h[nf], k1h[2 + nf]);
                    mma16816(a1[nf], qh[ks], k1l[nf], k1l[2 + nf]);
                    mma16816(a1[nf], ql[ks], k1h[nf], k1h[2 + nf]);
                    mma16816(a2[nf], qh[ks], k2h[nf], k2h[2 + nf]);
                    mma16816(a2[nf], qh[ks], k2l[nf], k2l[2 + nf]);
                    mma16816(a2[nf], ql[ks], k2h[nf], k2h[2 + nf]);
                }
            }

#pragma unroll
            for (int nf = 0; nf < 2; nf++)
#pragma unroll
                for (int e = 0; e < 2; e++) {
                    const int kg = kt * 64 + kp * 16 + nf * 8 + t4 * 2 + e;
                    const char km = sKm8[kg];
                    const char mk = sMk8[kg];
                    const float kgf = (float)kg;
#pragma unroll
                    for (int hf = 0; hf < 2; hf++) {
                        const float v = (qmv[hf] == km) ? a1[nf][hf * 2 + e]
                                                        : a2[nf][hf * 2 + e];
                        const float dd = qgf[hf] - kgf;
                        float s = v * 0.125f - (shiftv * dd * dd + biasv);
                        if (!mk) s = -1e30f;
                        sv[kp][nf][e][hf] = s;
                        cmax[hf] = fmaxf(cmax[hf], s);
                    }
                }
        }

        // ---- phase 2: one softmax update per 64-key chunk ----
#pragma unroll
        for (int hf = 0; hf < 2; hf++) {
            cmax[hf] = fmaxf(cmax[hf], __shfl_xor_sync(0xffffffffu, cmax[hf], 1));
            cmax[hf] = fmaxf(cmax[hf], __shfl_xor_sync(0xffffffffu, cmax[hf], 2));
        }
        float corr[2];
#pragma unroll
        for (int hf = 0; hf < 2; hf++) {
            const float nm = fmaxf(mx[hf], cmax[hf]);
            corr[hf] = __expf(mx[hf] - nm);
            mx[hf] = nm;
            sum[hf] *= corr[hf];
        }
#pragma unroll
        for (int d = 0; d < 8; d++) {
            o[d][0] *= corr[0]; o[d][1] *= corr[0];
            o[d][2] *= corr[1]; o[d][3] *= corr[1];
        }

        // ---- phase 3: exp + pack P fragments ----
        uint32_t pH[4][4], pL[4][4];
#pragma unroll
        for (int kp = 0; kp < 4; kp++)
#pragma unroll
            for (int nf = 0; nf < 2; nf++)
#pragma unroll
                for (int hf = 0; hf < 2; hf++) {
                    const float p0 = __expf(sv[kp][nf][0][hf] - mx[hf]);
                    const float p1 = __expf(sv[kp][nf][1][hf] - mx[hf]);
                    sum[hf] += p0 + p1;
                    const float h0 = __bfloat162float(__float2bfloat16(p0));
                    const float h1 = __bfloat162float(__float2bfloat16(p1));
                    const int idx = nf * 2 + hf;
                    pH[kp][idx] = pkbf2(p0, p1);
                    pL[kp][idx] = pkbf2(p0 - h0, p1 - h1);
                }

        // ---- phase 4: P @ V over the whole 64-key chunk ----
        const int quad = lane >> 3, r = lane & 7;
#pragma unroll
        for (int dblk = 0; dblk < 4; dblk++) {
#pragma unroll
            for (int kp = 0; kp < 4; kp++) {
                uint32_t vh[4], vl[4];
                uint32_t boff = sw128((uint32_t)((kp * 16 + (quad & 1) * 8 + r) * 128
                                                 + dblk * 32 + (quad >> 1) * 16));
                LDSM4T(vh[0], vh[1], vh[2], vh[3], kb + 32768 + boff);
                LDSM4T(vl[0], vl[1], vl[2], vl[3], kb + 40960 + boff);
#pragma unroll
                for (int nf = 0; nf < 2; nf++) {
                    mma16816(o[dblk * 2 + nf], pH[kp], vh[nf * 2], vh[nf * 2 + 1]);
                    mma16816(o[dblk * 2 + nf], pH[kp], vl[nf * 2], vl[nf * 2 + 1]);
                    mma16816(o[dblk * 2 + nf], pL[kp], vh[nf * 2], vh[nf * 2 + 1]);
                }
            }
        }
        __syncthreads();
        if (kt + 2 < 8) ldKV(kt & 1, kt + 2);
    }

    // finalize
    float inv[2];
#pragma unroll
    for (int hf = 0; hf < 2; hf++) {
        float s = sum[hf];
        s += __shfl_xor_sync(0xffffffffu, s, 1);
        s += __shfl_xor_sync(0xffffffffu, s, 2);
        inv[hf] = 1.0f / s;
    }
#pragma unroll
    for (int d = 0; d < 8; d++) {
        const int col = h * 64 + (d >> 1) * 16 + (d & 1) * 8 + t4 * 2;
#pragma unroll
        for (int hf = 0; hf < 2; hf++) {
            const size_t row = rowb + qt * 64 + w * 16 + g + hf * 8;
            const float v0 = o[d][hf * 2 + 0] * inv[hf];
            const float v1 = o[d][hf * 2 + 1] * inv[hf];
            const float h0 = __bfloat162float(__float2bfloat16(v0));
            const float h1 = __bfloat162float(__float2bfloat16(v1));
            *(uint32_t*)(g_Ah + row * DMODEL + col) = pkbf2(v0, v1);
            *(uint32_t*)(g_Al + row * DMODEL + col) = pkbf2(v0 - h0, v1 - h1);
        }
    }
}

// ---------------------------------------------------------------------------
extern "C" void kernel_launch(void* const* d_in, const int* in_sizes, int n_in,
                              void* d_out, int out_size)
{
    const float* x     = (const float*)d_in[0];
    const int*   mask  = (const int*)  d_in[1];
    const int*   qmask = (const int*)  d_in[2];
    const float* Wqkv  = (const float*)d_in[3];
    const float* fc_w  = (const float*)d_in[4];
    const float* fc_b  = (const float*)d_in[5];
    const float* shift = (const float*)d_in[6];
    const float* bias  = (const float*)d_in[7];
    float* out = (float*)d_out;

    __nv_bfloat16 *qh, *ql, *ah, *al, *bh, *bl, *wh, *wl;
    cudaGetSymbolAddress((void**)&qh, g_Qh);
    cudaGetSymbolAddress((void**)&ql, g_Ql);
    cudaGetSymbolAddress((void**)&ah, g_Ah);
    cudaGetSymbolAddress((void**)&al, g_Al);
    cudaGetSymbolAddress((void**)&bh, g_Bh);
    cudaGetSymbolAddress((void**)&bl, g_Bl);
    cudaGetSymbolAddress((void**)&wh, g_Wh);
    cudaGetSymbolAddress((void**)&wl, g_Wl);

    cudaFuncSetAttribute(gemm_hmma<true>,  cudaFuncAttributeMaxDynamicSharedMemorySize, 4 * G_STAGE);
    cudaFuncSetAttribute(gemm_hmma<false>, cudaFuncAttributeMaxDynamicSharedMemorySize, 4 * G_STAGE);
    cudaFuncSetAttribute(attn_flash, cudaFuncAttributeMaxDynamicSharedMemorySize, A_SMEM);

    // 1) fused splits
    {
        const int total = 2 * N_A4 + N_W4;
        split3<<<(total + 255) / 256, 256>>>((const float4*)x, (const float4*)Wqkv,
                                             (const float4*)fc_w);
    }

    // 2) qkv = x @ Wqkv^T, epilogue writes hi/lo bf16 directly
    {
        dim3 grid(4 * DMODEL / 128, MROWS / 64);    // (32, 64)
        gemm_hmma<true><<<grid, 128, 4 * G_STAGE>>>(ah, al, bh, bl, nullptr, nullptr,
                                                    qh, ql, 4 * DMODEL, DMODEL);
    }

    // 3) flash attention (HMMA), writes hi/lo att into g_Ah/g_Al
    {
        dim3 grid(SEQ / 64, NHEAD, BATCH);          // (8, 16, 8)
        attn_flash<<<grid, 128, A_SMEM>>>(mask, qmask, shift, bias);
    }

    // 4) out = att @ fc_w^T + fc_b (fp32 epilogue)
    {
        dim3 grid(DMODEL / 128, MROWS / 64);        // (8, 64)
        gemm_hmma<false><<<grid, 128, 4 * G_STAGE>>>(ah, al, wh, wl, fc_b, out,
                                                     nullptr, nullptr, DMODEL, DMODEL);
    }
}

// round 13
// speedup vs baseline: 1.5435x; 1.5435x over previous
#include <cuda_runtime.h>
#include <cuda_fp16.h>
#include <math.h>
#include <stdint.h>

#define BATCH 8
#define SEQ   512
#define DMODEL 1024
#define NHEAD 16
#define DHEAD 64
#define MROWS (BATCH*SEQ)        // 4096

// ---------------- scratch (no cudaMalloc allowed) ----------------
__device__ __half g_Qh[(size_t)MROWS * 4 * DMODEL];  // qkv hi (32MB)
__device__ __half g_Ql[(size_t)MROWS * 4 * DMODEL];  // qkv lo (32MB)
__device__ __half g_Ah[(size_t)MROWS * DMODEL];      // x/att split hi
__device__ __half g_Al[(size_t)MROWS * DMODEL];      // x/att split lo
__device__ __half g_Bh[(size_t)MROWS * DMODEL];      // Wqkv hi (lo not needed)
__device__ __half g_Wh[(size_t)DMODEL * DMODEL];     // fc_w hi (lo not needed)

// ---------------------------------------------------------------------------
__device__ __forceinline__ uint32_t pkh2(float a, float b) {
    __half2 t = __floats2half2_rn(a, b);
    return *reinterpret_cast<uint32_t*>(&t);
}

#define N_A4 (MROWS * DMODEL / 4)
#define N_W4 (DMODEL * DMODEL / 4)
// x -> hi+lo ; Wqkv -> hi only ; fc_w -> hi only
__global__ void split3(const float4* __restrict__ x, const float4* __restrict__ wqkv,
                       const float4* __restrict__ fcw)
{
    int i = blockIdx.x * blockDim.x + threadIdx.x;
    const float4* src;
    uint2 *hi, *lo;
    int j;
    if (i < N_A4) {
        src = x;    hi = (uint2*)g_Ah; lo = (uint2*)g_Al; j = i;
    } else if (i < 2 * N_A4) {
        src = wqkv; hi = (uint2*)g_Bh; lo = nullptr;      j = i - N_A4;
    } else if (i < 2 * N_A4 + N_W4) {
        src = fcw;  hi = (uint2*)g_Wh; lo = nullptr;      j = i - 2 * N_A4;
    } else return;

    float4 v = src[j];
    uint2 H;
    H.x = pkh2(v.x, v.y);  H.y = pkh2(v.z, v.w);
    hi[j] = H;
    if (lo) {
        float h0 = __half2float(__float2half(v.x));
        float h1 = __half2float(__float2half(v.y));
        float h2 = __half2float(__float2half(v.z));
        float h3 = __half2float(__float2half(v.w));
        uint2 L;
        L.x = pkh2(v.x - h0, v.y - h1);  L.y = pkh2(v.z - h2, v.w - h3);
        lo[j] = L;
    }
}

// ---------------------------------------------------------------------------
#define LDSM4(R0,R1,R2,R3,addr) \
    asm volatile("ldmatrix.sync.aligned.m8n8.x4.shared.b16 {%0,%1,%2,%3}, [%4];" \
        : "=r"(R0),"=r"(R1),"=r"(R2),"=r"(R3) : "r"(addr))
#define LDSM4T(R0,R1,R2,R3,addr) \
    asm volatile("ldmatrix.sync.aligned.m8n8.x4.trans.shared.b16 {%0,%1,%2,%3}, [%4];" \
        : "=r"(R0),"=r"(R1),"=r"(R2),"=r"(R3) : "r"(addr))
#define CPASYNC16(dst, src) \
    asm volatile("cp.async.cg.shared.global [%0], [%1], 16;" :: "r"(dst), "l"(src))
#define CPCOMMIT() asm volatile("cp.async.commit_group;")
#define CPWAIT(n)  asm volatile("cp.async.wait_group %0;" :: "n"(n))

__device__ __forceinline__ void mma16816(float* c, const uint32_t* a,
                                         uint32_t b0, uint32_t b1)
{
    asm volatile(
        "mma.sync.aligned.m16n8k16.row.col.f32.f16.f16.f32 "
        "{%0,%1,%2,%3}, {%4,%5,%6,%7}, {%8,%9}, {%0,%1,%2,%3};"
        : "+f"(c[0]), "+f"(c[1]), "+f"(c[2]), "+f"(c[3])
        : "r"(a[0]), "r"(a[1]), "r"(a[2]), "r"(a[3]), "r"(b0), "r"(b1));
}

__device__ __forceinline__ uint32_t sw128(uint32_t off) {
    return off ^ ((off >> 3) & 0x70);
}

// ---------------------------------------------------------------------------
// HMMA fp16 2-term GEMM (NT): C = (Ah+Al) @ Bh^T (+bias).
// CTA 64x128, 128 threads (warp 32x64), BK=64, 2-stage, 3 CTAs/SM.
// Stage: Ah 8K | Al 8K | Bh 16K = 32KB.
// ---------------------------------------------------------------------------
#define G_AH 0
#define G_AL 8192
#define G_BH 16384
#define G_STAGE 32768

template<bool SPLIT>
__global__ __launch_bounds__(128, 3)
void gemm_hmma(const __half* __restrict__ Ah, const __half* __restrict__ Al,
               const __half* __restrict__ Bh,
               const float* __restrict__ bias, float* __restrict__ C,
               __half* __restrict__ Ch, __half* __restrict__ Cl,
               int N, int K)
{
    extern __shared__ __align__(1024) char smem[];   // 2 x 32KB stages
    const int tid  = threadIdx.x;
    const int wid  = tid >> 5;
    const int lane = tid & 31;
    const int bm   = blockIdx.y * 64;
    const int bn   = blockIdx.x * 128;
    const int wm   = (wid & 1) * 32;
    const int wn   = (wid >> 1) * 64;

    const uint32_t smem_u = (uint32_t)__cvta_generic_to_shared(smem);

    float acc[2][8][4];
#pragma unroll
    for (int i = 0; i < 2; i++)
#pragma unroll
        for (int j = 0; j < 8; j++)
#pragma unroll
            for (int q = 0; q < 4; q++) acc[i][j][q] = 0.f;

    auto load_chunk = [&](int buf, int kc) {
        const int k0 = kc * 64;
        const uint32_t base = smem_u + buf * G_STAGE;
#pragma unroll
        for (int j = 0; j < 4; j++) {
            const int slot = j * 128 + tid;
            const int row = slot >> 3, sl = slot & 7;
            uint32_t off = sw128((uint32_t)(row * 128 + sl * 16));
            CPASYNC16(base + G_AH + off, Ah + (size_t)(bm + row) * K + k0 + sl * 8);
            CPASYNC16(base + G_AL + off, Al + (size_t)(bm + row) * K + k0 + sl * 8);
        }
#pragma unroll
        for (int j = 0; j < 8; j++) {
            const int slot = j * 128 + tid;
            const int row = slot >> 3, sl = slot & 7;
            uint32_t off = sw128((uint32_t)(row * 128 + sl * 16));
            CPASYNC16(base + G_BH + off, Bh + (size_t)(bn + row) * K + k0 + sl * 8);
        }
        CPCOMMIT();
    };

    const int NC = K / 64;
    load_chunk(0, 0);
    load_chunk(1, 1);

    const int lrow = lane & 15;
    const int lhi  = lane >> 4;

    for (int c = 0; c < NC; c++) {
        if (c == NC - 1) { CPWAIT(0); } else { CPWAIT(1); }
        __syncthreads();
        const uint32_t b = smem_u + (c & 1) * G_STAGE;

#pragma unroll
        for (int ks = 0; ks < 4; ks++) {
            uint32_t ah[2][4], al[2][4];
#pragma unroll
            for (int mi = 0; mi < 2; mi++) {
                const int row = wm + mi * 16 + lrow;
                uint32_t off = sw128((uint32_t)(row * 128 + (ks * 2 + lhi) * 16));
                LDSM4(ah[mi][0], ah[mi][1], ah[mi][2], ah[mi][3], b + G_AH + off);
                LDSM4(al[mi][0], al[mi][1], al[mi][2], al[mi][3], b + G_AL + off);
            }
#pragma unroll
            for (int np = 0; np < 4; np++) {
                uint32_t bh[4];
                const int row = wn + np * 16 + lrow;
                uint32_t off = sw128((uint32_t)(row * 128 + (ks * 2 + lhi) * 16));
                LDSM4(bh[0], bh[1], bh[2], bh[3], b + G_BH + off);
#pragma unroll
                for (int mi = 0; mi < 2; mi++)
#pragma unroll
                    for (int hf = 0; hf < 2; hf++) {
                        const int nj = np * 2 + hf;
                        mma16816(acc[mi][nj], ah[mi], bh[hf], bh[2 + hf]);
                        mma16816(acc[mi][nj], al[mi], bh[hf], bh[2 + hf]);
                    }
            }
        }
        __syncthreads();
        if (c + 2 < NC) load_chunk(c & 1, c + 2);
    }

#pragma unroll
    for (int mi = 0; mi < 2; mi++) {
        const int m0 = bm + wm + mi * 16 + (lane >> 2);
#pragma unroll
        for (int nj = 0; nj < 8; nj++) {
            const int n0 = bn + wn + nj * 8 + (lane & 3) * 2;
#pragma unroll
            for (int hh = 0; hh < 2; hh++) {
                const int m = m0 + hh * 8;
                float v0 = acc[mi][nj][hh * 2 + 0];
                float v1 = acc[mi][nj][hh * 2 + 1];
                if (SPLIT) {
                    float h0 = __half2float(__float2half(v0));
                    float h1 = __half2float(__float2half(v1));
                    *(uint32_t*)(Ch + (size_t)m * N + n0) = pkh2(v0, v1);
                    *(uint32_t*)(Cl + (size_t)m * N + n0) = pkh2(v0 - h0, v1 - h1);
                } else {
                    float2 v;
                    v.x = v0 + bias[n0];
                    v.y = v1 + bias[n0 + 1];
                    *(float2*)(C + (size_t)m * N + n0) = v;
                }
            }
        }
    }
}

// ---------------------------------------------------------------------------
// Flash attention, fp16 2-term.  Scores = (Qh+Ql)·K1h/K2h; PV = (Ph+Pl)·Vh.
// CTA = 128 threads (4 warps), 64 queries per (b,h,qt). 2 CTAs/SM.
// KV chunk: k1h 8K | k2h 8K | vh 8K = 24KB, double-buffered.
// ---------------------------------------------------------------------------
#define A_OFF_KV 16384
#define A_OFF_KM 65536              // 16384 + 2*24576
#define A_OFF_MK 66048
#define A_SMEM   66560

__global__ __launch_bounds__(128, 2)
void attn_flash(const int* __restrict__ mask, const int* __restrict__ qmask,
                const float* __restrict__ shiftp, const float* __restrict__ biasp)
{
    extern __shared__ __align__(1024) char sm8[];
    const int tid  = threadIdx.x;
    const int lane = tid & 31;
    const int w    = tid >> 5;
    const int qt = blockIdx.x, h = blockIdx.y, b = blockIdx.z;
    const int lrow = lane & 15, lhi = lane >> 4;
    const int g = lane >> 2, t4 = lane & 3;

    const uint32_t su  = (uint32_t)__cvta_generic_to_shared(sm8);
    const uint32_t uKV = su + A_OFF_KV;
    char* sKm8 = sm8 + A_OFF_KM;
    char* sMk8 = sm8 + A_OFF_MK;

    const float shiftv = shiftp[0];
    const float biasv  = biasp[0];
    const size_t rowb  = (size_t)b * SEQ;

    for (int i = tid; i < 512; i += 128) {
        sKm8[i] = (char)qmask[rowb + i];
        sMk8[i] = (char)mask [rowb + i];
    }

    // Q tile (hi/lo)
#pragma unroll
    for (int t = 0; t < 2; t++) {
        const __half* src = t ? g_Ql : g_Qh;
#pragma unroll
        for (int j = 0; j < 4; j++) {
            const int slot = j * 128 + tid;
            const int row = slot >> 3, sl = slot & 7;
            CPASYNC16(su + t * 8192 + sw128((uint32_t)(row * 128 + sl * 16)),
                      src + (rowb + qt * 64 + row) * 4096 + h * 64 + sl * 8);
        }
    }
    CPCOMMIT();

    // chunk loader: k1h, k2h, vh (hi only)
    auto ldKV = [&](int buf, int kt) {
        const uint32_t base = uKV + buf * 24576;
#pragma unroll
        for (int t = 0; t < 3; t++) {
            const int colb = (t + 1) * 1024 + h * 64;
#pragma unroll
            for (int j = 0; j < 4; j++) {
                const int slot = j * 128 + tid;
                const int row = slot >> 3, sl = slot & 7;
                CPASYNC16(base + t * 8192 + sw128((uint32_t)(row * 128 + sl * 16)),
                          g_Qh + (rowb + kt * 64 + row) * 4096 + colb + sl * 8);
            }
        }
        CPCOMMIT();
    };

    ldKV(0, 0);
    ldKV(1, 1);

    CPWAIT(2);                  // Q landed
    __syncthreads();

    uint32_t qh[4][4], ql[4][4];
#pragma unroll
    for (int ks = 0; ks < 4; ks++) {
        uint32_t off = sw128((uint32_t)((w * 16 + lrow) * 128 + (ks * 2 + lhi) * 16));
        LDSM4(qh[ks][0], qh[ks][1], qh[ks][2], qh[ks][3], su + off);
        LDSM4(ql[ks][0], ql[ks][1], ql[ks][2], ql[ks][3], su + 8192 + off);
    }

    char  qmv[2];
    float qgf[2];
#pragma unroll
    for (int hf = 0; hf < 2; hf++) {
        const int qr = qt * 64 + w * 16 + g + hf * 8;
        qmv[hf] = sKm8[qr];
        qgf[hf] = (float)qr;
    }

    float o[8][4];
#pragma unroll
    for (int d = 0; d < 8; d++)
#pragma unroll
        for (int q = 0; q < 4; q++) o[d][q] = 0.f;
    float mx[2] = {-1e30f, -1e30f};
    float sum[2] = {0.f, 0.f};

    for (int kt = 0; kt < 8; kt++) {
        if (kt == 7) { CPWAIT(0); } else { CPWAIT(1); }
        __syncthreads();
        const uint32_t kb = uKV + (kt & 1) * 24576;

        // ---- phase 1: scores for all 64 keys of this chunk ----
        float sv[4][2][2][2];               // [kp][nf][e][hf]
        float cmax[2] = {-1e30f, -1e30f};
#pragma unroll
        for (int kp = 0; kp < 4; kp++) {
            float a1[2][4], a2[2][4];
#pragma unroll
            for (int nf = 0; nf < 2; nf++)
#pragma unroll
                for (int q = 0; q < 4; q++) { a1[nf][q] = 0.f; a2[nf][q] = 0.f; }

#pragma unroll
            for (int ks = 0; ks < 4; ks++) {
                uint32_t k1h[4], k2h[4];
                uint32_t off = sw128((uint32_t)((kp * 16 + lrow) * 128 + (ks * 2 + lhi) * 16));
                LDSM4(k1h[0], k1h[1], k1h[2], k1h[3], kb + off);
                LDSM4(k2h[0], k2h[1], k2h[2], k2h[3], kb + 8192 + off);
#pragma unroll
                for (int nf = 0; nf < 2; nf++) {
                    mma16816(a1[nf], qh[ks], k1h[nf], k1h[2 + nf]);
                    mma16816(a1[nf], ql[ks], k1h[nf], k1h[2 + nf]);
                    mma16816(a2[nf], qh[ks], k2h[nf], k2h[2 + nf]);
                    mma16816(a2[nf], ql[ks], k2h[nf], k2h[2 + nf]);
                }
            }

#pragma unroll
            for (int nf = 0; nf < 2; nf++)
#pragma unroll
                for (int e = 0; e < 2; e++) {
                    const int kg = kt * 64 + kp * 16 + nf * 8 + t4 * 2 + e;
                    const char km = sKm8[kg];
                    const char mk = sMk8[kg];
                    const float kgf = (float)kg;
#pragma unroll
                    for (int hf = 0; hf < 2; hf++) {
                        const float v = (qmv[hf] == km) ? a1[nf][hf * 2 + e]
                                                        : a2[nf][hf * 2 + e];
                        const float dd = qgf[hf] - kgf;
                        float s = v * 0.125f - (shiftv * dd * dd + biasv);
                        if (!mk) s = -1e30f;
                        sv[kp][nf][e][hf] = s;
                        cmax[hf] = fmaxf(cmax[hf], s);
                    }
                }
        }

        // ---- phase 2: one softmax update per 64-key chunk ----
#pragma unroll
        for (int hf = 0; hf < 2; hf++) {
            cmax[hf] = fmaxf(cmax[hf], __shfl_xor_sync(0xffffffffu, cmax[hf], 1));
            cmax[hf] = fmaxf(cmax[hf], __shfl_xor_sync(0xffffffffu, cmax[hf], 2));
        }
        float corr[2];
#pragma unroll
        for (int hf = 0; hf < 2; hf++) {
            const float nm = fmaxf(mx[hf], cmax[hf]);
            corr[hf] = __expf(mx[hf] - nm);
            mx[hf] = nm;
            sum[hf] *= corr[hf];
        }
#pragma unroll
        for (int d = 0; d < 8; d++) {
            o[d][0] *= corr[0]; o[d][1] *= corr[0];
            o[d][2] *= corr[1]; o[d][3] *= corr[1];
        }

        // ---- phase 3: exp + pack P fragments (fp16 hi/lo) ----
        uint32_t pH[4][4], pL[4][4];
#pragma unroll
        for (int kp = 0; kp < 4; kp++)
#pragma unroll
            for (int nf = 0; nf < 2; nf++)
#pragma unroll
                for (int hf = 0; hf < 2; hf++) {
                    const float p0 = __expf(sv[kp][nf][0][hf] - mx[hf]);
                    const float p1 = __expf(sv[kp][nf][1][hf] - mx[hf]);
                    sum[hf] += p0 + p1;
                    const float h0 = __half2float(__float2half(p0));
                    const float h1 = __half2float(__float2half(p1));
                    const int idx = nf * 2 + hf;
                    pH[kp][idx] = pkh2(p0, p1);
                    pL[kp][idx] = pkh2(p0 - h0, p1 - h1);
                }

        // ---- phase 4: P @ Vh over the 64-key chunk ----
        const int quad = lane >> 3, r = lane & 7;
#pragma unroll
        for (int dblk = 0; dblk < 4; dblk++) {
#pragma unroll
            for (int kp = 0; kp < 4; kp++) {
                uint32_t vh[4];
                uint32_t boff = sw128((uint32_t)((kp * 16 + (quad & 1) * 8 + r) * 128
                                                 + dblk * 32 + (quad >> 1) * 16));
                LDSM4T(vh[0], vh[1], vh[2], vh[3], kb + 16384 + boff);
#pragma unroll
                for (int nf = 0; nf < 2; nf++) {
                    mma16816(o[dblk * 2 + nf], pH[kp], vh[nf * 2], vh[nf * 2 + 1]);
                    mma16816(o[dblk * 2 + nf], pL[kp], vh[nf * 2], vh[nf * 2 + 1]);
                }
            }
        }
        __syncthreads();
        if (kt + 2 < 8) ldKV(kt & 1, kt + 2);
    }

    // finalize
    float inv[2];
#pragma unroll
    for (int hf = 0; hf < 2; hf++) {
        float s = sum[hf];
        s += __shfl_xor_sync(0xffffffffu, s, 1);
        s += __shfl_xor_sync(0xffffffffu, s, 2);
        inv[hf] = 1.0f / s;
    }
#pragma unroll
    for (int d = 0; d < 8; d++) {
        const int col = h * 64 + (d >> 1) * 16 + (d & 1) * 8 + t4 * 2;
#pragma unroll
        for (int hf = 0; hf < 2; hf++) {
            const size_t row = rowb + qt * 64 + w * 16 + g + hf * 8;
            const float v0 = o[d][hf * 2 + 0] * inv[hf];
            const float v1 = o[d][hf * 2 + 1] * inv[hf];
            const float h0 = __half2float(__float2half(v0));
            const float h1 = __half2float(__float2half(v1));
            *(uint32_t*)(g_Ah + row * DMODEL + col) = pkh2(v0, v1);
            *(uint32_t*)(g_Al + row * DMODEL + col) = pkh2(v0 - h0, v1 - h1);
        }
    }
}

// ---------------------------------------------------------------------------
extern "C" void kernel_launch(void* const* d_in, const int* in_sizes, int n_in,
                              void* d_out, int out_size)
{
    const float* x     = (const float*)d_in[0];
    const int*   mask  = (const int*)  d_in[1];
    const int*   qmask = (const int*)  d_in[2];
    const float* Wqkv  = (const float*)d_in[3];
    const float* fc_w  = (const float*)d_in[4];
    const float* fc_b  = (const float*)d_in[5];
    const float* shift = (const float*)d_in[6];
    const float* bias  = (const float*)d_in[7];
    float* out = (float*)d_out;

    __half *qh, *ql, *ah, *al, *bh, *wh;
    cudaGetSymbolAddress((void**)&qh, g_Qh);
    cudaGetSymbolAddress((void**)&ql, g_Ql);
    cudaGetSymbolAddress((void**)&ah, g_Ah);
    cudaGetSymbolAddress((void**)&al, g_Al);
    cudaGetSymbolAddress((void**)&bh, g_Bh);
    cudaGetSymbolAddress((void**)&wh, g_Wh);

    cudaFuncSetAttribute(gemm_hmma<true>,  cudaFuncAttributeMaxDynamicSharedMemorySize, 2 * G_STAGE);
    cudaFuncSetAttribute(gemm_hmma<false>, cudaFuncAttributeMaxDynamicSharedMemorySize, 2 * G_STAGE);
    cudaFuncSetAttribute(attn_flash, cudaFuncAttributeMaxDynamicSharedMemorySize, A_SMEM);

    // 1) fused splits: x -> Ah/Al, Wqkv -> Bh, fc_w -> Wh
    {
        const int total = 2 * N_A4 + N_W4;
        split3<<<(total + 255) / 256, 256>>>((const float4*)x, (const float4*)Wqkv,
                                             (const float4*)fc_w);
    }

    // 2) qkv = x @ Wqkv^T, epilogue writes hi/lo fp16 directly
    {
        dim3 grid(4 * DMODEL / 128, MROWS / 64);    // (32, 64)
        gemm_hmma<true><<<grid, 128, 2 * G_STAGE>>>(ah, al, bh, nullptr, nullptr,
                                                    qh, ql, 4 * DMODEL, DMODEL);
    }

    // 3) flash attention, writes hi/lo att into g_Ah/g_Al
    {
        dim3 grid(SEQ / 64, NHEAD, BATCH);          // (8, 16, 8)
        attn_flash<<<grid, 128, A_SMEM>>>(mask, qmask, shift, bias);
    }

    // 4) out = att @ fc_w^T + fc_b (fp32 epilogue)
    {
        dim3 grid(DMODEL / 128, MROWS / 64);        // (8, 64)
        gemm_hmma<false><<<grid, 128, 2 * G_STAGE>>>(ah, al, wh, fc_b, out,
                                                     nullptr, nullptr, DMODEL, DMODEL);
    }
}

// round 14
// speedup vs baseline: 1.5809x; 1.0243x over previous
#include <cuda_runtime.h>
#include <cuda_fp16.h>
#include <math.h>
#include <stdint.h>

#define BATCH 8
#define SEQ   512
#define DMODEL 1024
#define NHEAD 16
#define DHEAD 64
#define MROWS (BATCH*SEQ)        // 4096

// ---------------- scratch (no cudaMalloc allowed) ----------------
__device__ __half g_Qh[(size_t)MROWS * 4 * DMODEL];  // qkv hi (32MB)
__device__ __half g_Ql[(size_t)MROWS * 4 * DMODEL];  // qkv lo (only Q block used)
__device__ __half g_Ah[(size_t)MROWS * DMODEL];      // x/att split hi
__device__ __half g_Al[(size_t)MROWS * DMODEL];      // x/att split lo
__device__ __half g_Bh[(size_t)MROWS * DMODEL];      // Wqkv hi
__device__ __half g_Wh[(size_t)DMODEL * DMODEL];     // fc_w hi

// ---------------------------------------------------------------------------
__device__ __forceinline__ uint32_t pkh2(float a, float b) {
    __half2 t = __floats2half2_rn(a, b);
    return *reinterpret_cast<uint32_t*>(&t);
}

#define N_A4 (MROWS * DMODEL / 4)
#define N_W4 (DMODEL * DMODEL / 4)
// x -> hi+lo ; Wqkv -> hi only ; fc_w -> hi only
__global__ void split3(const float4* __restrict__ x, const float4* __restrict__ wqkv,
                       const float4* __restrict__ fcw)
{
    int i = blockIdx.x * blockDim.x + threadIdx.x;
    const float4* src;
    uint2 *hi, *lo;
    int j;
    if (i < N_A4) {
        src = x;    hi = (uint2*)g_Ah; lo = (uint2*)g_Al; j = i;
    } else if (i < 2 * N_A4) {
        src = wqkv; hi = (uint2*)g_Bh; lo = nullptr;      j = i - N_A4;
    } else if (i < 2 * N_A4 + N_W4) {
        src = fcw;  hi = (uint2*)g_Wh; lo = nullptr;      j = i - 2 * N_A4;
    } else return;

    float4 v = src[j];
    uint2 H;
    H.x = pkh2(v.x, v.y);  H.y = pkh2(v.z, v.w);
    hi[j] = H;
    if (lo) {
        float h0 = __half2float(__float2half(v.x));
        float h1 = __half2float(__float2half(v.y));
        float h2 = __half2float(__float2half(v.z));
        float h3 = __half2float(__float2half(v.w));
        uint2 L;
        L.x = pkh2(v.x - h0, v.y - h1);  L.y = pkh2(v.z - h2, v.w - h3);
        lo[j] = L;
    }
}

// ---------------------------------------------------------------------------
#define LDSM4(R0,R1,R2,R3,addr) \
    asm volatile("ldmatrix.sync.aligned.m8n8.x4.shared.b16 {%0,%1,%2,%3}, [%4];" \
        : "=r"(R0),"=r"(R1),"=r"(R2),"=r"(R3) : "r"(addr))
#define LDSM4T(R0,R1,R2,R3,addr) \
    asm volatile("ldmatrix.sync.aligned.m8n8.x4.trans.shared.b16 {%0,%1,%2,%3}, [%4];" \
        : "=r"(R0),"=r"(R1),"=r"(R2),"=r"(R3) : "r"(addr))
#define CPASYNC16(dst, src) \
    asm volatile("cp.async.cg.shared.global [%0], [%1], 16;" :: "r"(dst), "l"(src))
#define CPCOMMIT() asm volatile("cp.async.commit_group;")
#define CPWAIT(n)  asm volatile("cp.async.wait_group %0;" :: "n"(n))

__device__ __forceinline__ void mma16816(float* c, const uint32_t* a,
                                         uint32_t b0, uint32_t b1)
{
    asm volatile(
        "mma.sync.aligned.m16n8k16.row.col.f32.f16.f16.f32 "
        "{%0,%1,%2,%3}, {%4,%5,%6,%7}, {%8,%9}, {%0,%1,%2,%3};"
        : "+f"(c[0]), "+f"(c[1]), "+f"(c[2]), "+f"(c[3])
        : "r"(a[0]), "r"(a[1]), "r"(a[2]), "r"(a[3]), "r"(b0), "r"(b1));
}

__device__ __forceinline__ uint32_t sw128(uint32_t off) {
    return off ^ ((off >> 3) & 0x70);
}

// ---------------------------------------------------------------------------
// HMMA fp16 2-term GEMM (NT): C = (Ah+Al) @ Bh^T (+bias).
// CTA 64x128, 128 threads (warp 32x64), BK=64, 2-stage, 3 CTAs/SM.
// loN: write Cl only for output columns < loN (dead-store elimination).
// ---------------------------------------------------------------------------
#define G_AH 0
#define G_AL 8192
#define G_BH 16384
#define G_STAGE 32768

template<bool SPLIT>
__global__ __launch_bounds__(128, 3)
void gemm_hmma(const __half* __restrict__ Ah, const __half* __restrict__ Al,
               const __half* __restrict__ Bh,
               const float* __restrict__ bias, float* __restrict__ C,
               __half* __restrict__ Ch, __half* __restrict__ Cl,
               int N, int K, int loN)
{
    extern __shared__ __align__(1024) char smem[];   // 2 x 32KB stages
    const int tid  = threadIdx.x;
    const int wid  = tid >> 5;
    const int lane = tid & 31;
    const int bm   = blockIdx.y * 64;
    const int bn   = blockIdx.x * 128;
    const int wm   = (wid & 1) * 32;
    const int wn   = (wid >> 1) * 64;

    const uint32_t smem_u = (uint32_t)__cvta_generic_to_shared(smem);

    float acc[2][8][4];
#pragma unroll
    for (int i = 0; i < 2; i++)
#pragma unroll
        for (int j = 0; j < 8; j++)
#pragma unroll
            for (int q = 0; q < 4; q++) acc[i][j][q] = 0.f;

    auto load_chunk = [&](int buf, int kc) {
        const int k0 = kc * 64;
        const uint32_t base = smem_u + buf * G_STAGE;
#pragma unroll
        for (int j = 0; j < 4; j++) {
            const int slot = j * 128 + tid;
            const int row = slot >> 3, sl = slot & 7;
            uint32_t off = sw128((uint32_t)(row * 128 + sl * 16));
            CPASYNC16(base + G_AH + off, Ah + (size_t)(bm + row) * K + k0 + sl * 8);
            CPASYNC16(base + G_AL + off, Al + (size_t)(bm + row) * K + k0 + sl * 8);
        }
#pragma unroll
        for (int j = 0; j < 8; j++) {
            const int slot = j * 128 + tid;
            const int row = slot >> 3, sl = slot & 7;
            uint32_t off = sw128((uint32_t)(row * 128 + sl * 16));
            CPASYNC16(base + G_BH + off, Bh + (size_t)(bn + row) * K + k0 + sl * 8);
        }
        CPCOMMIT();
    };

    const int NC = K / 64;
    load_chunk(0, 0);
    load_chunk(1, 1);

    const int lrow = lane & 15;
    const int lhi  = lane >> 4;

    for (int c = 0; c < NC; c++) {
        if (c == NC - 1) { CPWAIT(0); } else { CPWAIT(1); }
        __syncthreads();
        const uint32_t b = smem_u + (c & 1) * G_STAGE;

#pragma unroll
        for (int ks = 0; ks < 4; ks++) {
            uint32_t ah[2][4], al[2][4];
#pragma unroll
            for (int mi = 0; mi < 2; mi++) {
                const int row = wm + mi * 16 + lrow;
                uint32_t off = sw128((uint32_t)(row * 128 + (ks * 2 + lhi) * 16));
                LDSM4(ah[mi][0], ah[mi][1], ah[mi][2], ah[mi][3], b + G_AH + off);
                LDSM4(al[mi][0], al[mi][1], al[mi][2], al[mi][3], b + G_AL + off);
            }
#pragma unroll
            for (int np = 0; np < 4; np++) {
                uint32_t bh[4];
                const int row = wn + np * 16 + lrow;
                uint32_t off = sw128((uint32_t)(row * 128 + (ks * 2 + lhi) * 16));
                LDSM4(bh[0], bh[1], bh[2], bh[3], b + G_BH + off);
#pragma unroll
                for (int mi = 0; mi < 2; mi++)
#pragma unroll
                    for (int hf = 0; hf < 2; hf++) {
                        const int nj = np * 2 + hf;
                        mma16816(acc[mi][nj], ah[mi], bh[hf], bh[2 + hf]);
                        mma16816(acc[mi][nj], al[mi], bh[hf], bh[2 + hf]);
                    }
            }
        }
        __syncthreads();
        if (c + 2 < NC) load_chunk(c & 1, c + 2);
    }

    const bool write_lo = SPLIT && (bn < loN);   // uniform per CTA
#pragma unroll
    for (int mi = 0; mi < 2; mi++) {
        const int m0 = bm + wm + mi * 16 + (lane >> 2);
#pragma unroll
        for (int nj = 0; nj < 8; nj++) {
            const int n0 = bn + wn + nj * 8 + (lane & 3) * 2;
#pragma unroll
            for (int hh = 0; hh < 2; hh++) {
                const int m = m0 + hh * 8;
                float v0 = acc[mi][nj][hh * 2 + 0];
                float v1 = acc[mi][nj][hh * 2 + 1];
                if (SPLIT) {
                    *(uint32_t*)(Ch + (size_t)m * N + n0) = pkh2(v0, v1);
                    if (write_lo) {
                        float h0 = __half2float(__float2half(v0));
                        float h1 = __half2float(__float2half(v1));
                        *(uint32_t*)(Cl + (size_t)m * N + n0) = pkh2(v0 - h0, v1 - h1);
                    }
                } else {
                    float2 v;
                    v.x = v0 + bias[n0];
                    v.y = v1 + bias[n0 + 1];
                    *(float2*)(C + (size_t)m * N + n0) = v;
                }
            }
        }
    }
}

// ---------------------------------------------------------------------------
// Flash attention, fp16 2-term, 3 CTAs/SM.
// Scores = (Qh+Ql)·K1h/K2h; PV = (Ph+Pl)·Vh.
// KV chunk: k1h 8K | k2h 8K | vh 8K = 24KB, double-buffered.
// ---------------------------------------------------------------------------
#define A_OFF_KV 16384
#define A_OFF_KM 65536              // 16384 + 2*24576
#define A_OFF_MK 66048
#define A_SMEM   66560

__global__ __launch_bounds__(128, 3)
void attn_flash(const int* __restrict__ mask, const int* __restrict__ qmask,
                const float* __restrict__ shiftp, const float* __restrict__ biasp)
{
    extern __shared__ __align__(1024) char sm8[];
    const int tid  = threadIdx.x;
    const int lane = tid & 31;
    const int w    = tid >> 5;
    const int qt = blockIdx.x, h = blockIdx.y, b = blockIdx.z;
    const int lrow = lane & 15, lhi = lane >> 4;
    const int g = lane >> 2, t4 = lane & 3;

    const uint32_t su  = (uint32_t)__cvta_generic_to_shared(sm8);
    const uint32_t uKV = su + A_OFF_KV;
    char* sKm8 = sm8 + A_OFF_KM;
    char* sMk8 = sm8 + A_OFF_MK;

    const float shiftv = shiftp[0];
    const float biasv  = biasp[0];
    const size_t rowb  = (size_t)b * SEQ;

    for (int i = tid; i < 512; i += 128) {
        sKm8[i] = (char)qmask[rowb + i];
        sMk8[i] = (char)mask [rowb + i];
    }

    // Q tile (hi/lo)
#pragma unroll
    for (int t = 0; t < 2; t++) {
        const __half* src = t ? g_Ql : g_Qh;
#pragma unroll
        for (int j = 0; j < 4; j++) {
            const int slot = j * 128 + tid;
            const int row = slot >> 3, sl = slot & 7;
            CPASYNC16(su + t * 8192 + sw128((uint32_t)(row * 128 + sl * 16)),
                      src + (rowb + qt * 64 + row) * 4096 + h * 64 + sl * 8);
        }
    }
    CPCOMMIT();

    // chunk loader: k1h, k2h, vh (hi only)
    auto ldKV = [&](int buf, int kt) {
        const uint32_t base = uKV + buf * 24576;
#pragma unroll
        for (int t = 0; t < 3; t++) {
            const int colb = (t + 1) * 1024 + h * 64;
#pragma unroll
            for (int j = 0; j < 4; j++) {
                const int slot = j * 128 + tid;
                const int row = slot >> 3, sl = slot & 7;
                CPASYNC16(base + t * 8192 + sw128((uint32_t)(row * 128 + sl * 16)),
                          g_Qh + (rowb + kt * 64 + row) * 4096 + colb + sl * 8);
            }
        }
        CPCOMMIT();
    };

    ldKV(0, 0);
    ldKV(1, 1);

    CPWAIT(2);                  // Q landed
    __syncthreads();

    uint32_t qh[4][4], ql[4][4];
#pragma unroll
    for (int ks = 0; ks < 4; ks++) {
        uint32_t off = sw128((uint32_t)((w * 16 + lrow) * 128 + (ks * 2 + lhi) * 16));
        LDSM4(qh[ks][0], qh[ks][1], qh[ks][2], qh[ks][3], su + off);
        LDSM4(ql[ks][0], ql[ks][1], ql[ks][2], ql[ks][3], su + 8192 + off);
    }

    char  qmv[2];
    float qgf[2];
#pragma unroll
    for (int hf = 0; hf < 2; hf++) {
        const int qr = qt * 64 + w * 16 + g + hf * 8;
        qmv[hf] = sKm8[qr];
        qgf[hf] = (float)qr;
    }

    float o[8][4];
#pragma unroll
    for (int d = 0; d < 8; d++)
#pragma unroll
        for (int q = 0; q < 4; q++) o[d][q] = 0.f;
    float mx[2] = {-1e30f, -1e30f};
    float sum[2] = {0.f, 0.f};

    for (int kt = 0; kt < 8; kt++) {
        if (kt == 7) { CPWAIT(0); } else { CPWAIT(1); }
        __syncthreads();
        const uint32_t kb = uKV + (kt & 1) * 24576;

        // ---- phase 1: scores for all 64 keys of this chunk ----
        float sv[4][2][2][2];               // [kp][nf][e][hf]
        float cmax[2] = {-1e30f, -1e30f};
#pragma unroll
        for (int kp = 0; kp < 4; kp++) {
            float a1[2][4], a2[2][4];
#pragma unroll
            for (int nf = 0; nf < 2; nf++)
#pragma unroll
                for (int q = 0; q < 4; q++) { a1[nf][q] = 0.f; a2[nf][q] = 0.f; }

#pragma unroll
            for (int ks = 0; ks < 4; ks++) {
                uint32_t k1h[4], k2h[4];
                uint32_t off = sw128((uint32_t)((kp * 16 + lrow) * 128 + (ks * 2 + lhi) * 16));
                LDSM4(k1h[0], k1h[1], k1h[2], k1h[3], kb + off);
                LDSM4(k2h[0], k2h[1], k2h[2], k2h[3], kb + 8192 + off);
#pragma unroll
                for (int nf = 0; nf < 2; nf++) {
                    mma16816(a1[nf], qh[ks], k1h[nf], k1h[2 + nf]);
                    mma16816(a1[nf], ql[ks], k1h[nf], k1h[2 + nf]);
                    mma16816(a2[nf], qh[ks], k2h[nf], k2h[2 + nf]);
                    mma16816(a2[nf], ql[ks], k2h[nf], k2h[2 + nf]);
                }
            }

#pragma unroll
            for (int nf = 0; nf < 2; nf++)
#pragma unroll
                for (int e = 0; e < 2; e++) {
                    const int kg = kt * 64 + kp * 16 + nf * 8 + t4 * 2 + e;
                    const char km = sKm8[kg];
                    const char mk = sMk8[kg];
                    const float kgf = (float)kg;
#pragma unroll
                    for (int hf = 0; hf < 2; hf++) {
                        const float v = (qmv[hf] == km) ? a1[nf][hf * 2 + e]
                                                        : a2[nf][hf * 2 + e];
                        const float dd = qgf[hf] - kgf;
                        float s = v * 0.125f - (shiftv * dd * dd + biasv);
                        if (!mk) s = -1e30f;
                        sv[kp][nf][e][hf] = s;
                        cmax[hf] = fmaxf(cmax[hf], s);
                    }
                }
        }

        // ---- phase 2: one softmax update per 64-key chunk ----
#pragma unroll
        for (int hf = 0; hf < 2; hf++) {
            cmax[hf] = fmaxf(cmax[hf], __shfl_xor_sync(0xffffffffu, cmax[hf], 1));
            cmax[hf] = fmaxf(cmax[hf], __shfl_xor_sync(0xffffffffu, cmax[hf], 2));
        }
        float corr[2];
#pragma unroll
        for (int hf = 0; hf < 2; hf++) {
            const float nm = fmaxf(mx[hf], cmax[hf]);
            corr[hf] = __expf(mx[hf] - nm);
            mx[hf] = nm;
            sum[hf] *= corr[hf];
        }
#pragma unroll
        for (int d = 0; d < 8; d++) {
            o[d][0] *= corr[0]; o[d][1] *= corr[0];
            o[d][2] *= corr[1]; o[d][3] *= corr[1];
        }

        // ---- phase 3: exp + pack P fragments (fp16 hi/lo) ----
        uint32_t pH[4][4], pL[4][4];
#pragma unroll
        for (int kp = 0; kp < 4; kp++)
#pragma unroll
            for (int nf = 0; nf < 2; nf++)
#pragma unroll
                for (int hf = 0; hf < 2; hf++) {
                    const float p0 = __expf(sv[kp][nf][0][hf] - mx[hf]);
                    const float p1 = __expf(sv[kp][nf][1][hf] - mx[hf]);
                    sum[hf] += p0 + p1;
                    const float h0 = __half2float(__float2half(p0));
                    const float h1 = __half2float(__float2half(p1));
                    const int idx = nf * 2 + hf;
                    pH[kp][idx] = pkh2(p0, p1);
                    pL[kp][idx] = pkh2(p0 - h0, p1 - h1);
                }

        // ---- phase 4: P @ Vh over the 64-key chunk ----
        const int quad = lane >> 3, r = lane & 7;
#pragma unroll
        for (int dblk = 0; dblk < 4; dblk++) {
#pragma unroll
            for (int kp = 0; kp < 4; kp++) {
                uint32_t vh[4];
                uint32_t boff = sw128((uint32_t)((kp * 16 + (quad & 1) * 8 + r) * 128
                                                 + dblk * 32 + (quad >> 1) * 16));
                LDSM4T(vh[0], vh[1], vh[2], vh[3], kb + 16384 + boff);
#pragma unroll
                for (int nf = 0; nf < 2; nf++) {
                    mma16816(o[dblk * 2 + nf], pH[kp], vh[nf * 2], vh[nf * 2 + 1]);
                    mma16816(o[dblk * 2 + nf], pL[kp], vh[nf * 2], vh[nf * 2 + 1]);
                }
            }
        }
        __syncthreads();
        if (kt + 2 < 8) ldKV(kt & 1, kt + 2);
    }

    // finalize
    float inv[2];
#pragma unroll
    for (int hf = 0; hf < 2; hf++) {
        float s = sum[hf];
        s += __shfl_xor_sync(0xffffffffu, s, 1);
        s += __shfl_xor_sync(0xffffffffu, s, 2);
        inv[hf] = 1.0f / s;
    }
#pragma unroll
    for (int d = 0; d < 8; d++) {
        const int col = h * 64 + (d >> 1) * 16 + (d & 1) * 8 + t4 * 2;
#pragma unroll
        for (int hf = 0; hf < 2; hf++) {
            const size_t row = rowb + qt * 64 + w * 16 + g + hf * 8;
            const float v0 = o[d][hf * 2 + 0] * inv[hf];
            const float v1 = o[d][hf * 2 + 1] * inv[hf];
            const float h0 = __half2float(__float2half(v0));
            const float h1 = __half2float(__float2half(v1));
            *(uint32_t*)(g_Ah + row * DMODEL + col) = pkh2(v0, v1);
            *(uint32_t*)(g_Al + row * DMODEL + col) = pkh2(v0 - h0, v1 - h1);
        }
    }
}

// ---------------------------------------------------------------------------
extern "C" void kernel_launch(void* const* d_in, const int* in_sizes, int n_in,
                              void* d_out, int out_size)
{
    const float* x     = (const float*)d_in[0];
    const int*   mask  = (const int*)  d_in[1];
    const int*   qmask = (const int*)  d_in[2];
    const float* Wqkv  = (const float*)d_in[3];
    const float* fc_w  = (const float*)d_in[4];
    const float* fc_b  = (const float*)d_in[5];
    const float* shift = (const float*)d_in[6];
    const float* bias  = (const float*)d_in[7];
    float* out = (float*)d_out;

    __half *qh, *ql, *ah, *al, *bh, *wh;
    cudaGetSymbolAddress((void**)&qh, g_Qh);
    cudaGetSymbolAddress((void**)&ql, g_Ql);
    cudaGetSymbolAddress((void**)&ah, g_Ah);
    cudaGetSymbolAddress((void**)&al, g_Al);
    cudaGetSymbolAddress((void**)&bh, g_Bh);
    cudaGetSymbolAddress((void**)&wh, g_Wh);

    cudaFuncSetAttribute(gemm_hmma<true>,  cudaFuncAttributeMaxDynamicSharedMemorySize, 2 * G_STAGE);
    cudaFuncSetAttribute(gemm_hmma<false>, cudaFuncAttributeMaxDynamicSharedMemorySize, 2 * G_STAGE);
    cudaFuncSetAttribute(attn_flash, cudaFuncAttributeMaxDynamicSharedMemorySize, A_SMEM);

    // 1) fused splits: x -> Ah/Al, Wqkv -> Bh, fc_w -> Wh
    {
        const int total = 2 * N_A4 + N_W4;
        split3<<<(total + 255) / 256, 256>>>((const float4*)x, (const float4*)Wqkv,
                                             (const float4*)fc_w);
    }

    // 2) qkv = x @ Wqkv^T, epilogue writes hi fp16; lo only for Q columns
    {
        dim3 grid(4 * DMODEL / 128, MROWS / 64);    // (32, 64)
        gemm_hmma<true><<<grid, 128, 2 * G_STAGE>>>(ah, al, bh, nullptr, nullptr,
                                                    qh, ql, 4 * DMODEL, DMODEL, DMODEL);
    }

    // 3) flash attention, writes hi/lo att into g_Ah/g_Al
    {
        dim3 grid(SEQ / 64, NHEAD, BATCH);          // (8, 16, 8)
        attn_flash<<<grid, 128, A_SMEM>>>(mask, qmask, shift, bias);
    }

    // 4) out = att @ fc_w^T + fc_b (fp32 epilogue)
    {
        dim3 grid(DMODEL / 128, MROWS / 64);        // (8, 64)
        gemm_hmma<false><<<grid, 128, 2 * G_STAGE>>>(ah, al, wh, fc_b, out,
                                                     nullptr, nullptr, DMODEL, DMODEL, 0);
    }
}

// round 15
// speedup vs baseline: 2.4323x; 1.5386x over previous
#include <cuda_runtime.h>
#include <cuda_fp16.h>
#include <math.h>
#include <stdint.h>

#define BATCH 8
#define SEQ   512
#define DMODEL 1024
#define NHEAD 16
#define DHEAD 64
#define MROWS (BATCH*SEQ)        // 4096

// ---------------- scratch (no cudaMalloc allowed) ----------------
__device__ __half g_Qh[(size_t)MROWS * 4 * DMODEL];  // qkv fp16 (32MB)
__device__ __half g_Ah[(size_t)MROWS * DMODEL];      // x fp16 / att fp16
__device__ __half g_Bh[(size_t)MROWS * DMODEL];      // Wqkv fp16
__device__ __half g_Wh[(size_t)DMODEL * DMODEL];     // fc_w fp16

// ---------------------------------------------------------------------------
__device__ __forceinline__ uint32_t pkh2(float a, float b) {
    __half2 t = __floats2half2_rn(a, b);
    return *reinterpret_cast<uint32_t*>(&t);
}

#define N_A4 (MROWS * DMODEL / 4)
#define N_W4 (DMODEL * DMODEL / 4)
// fp16 conversion: x -> Ah, Wqkv -> Bh, fc_w -> Wh
__global__ void cvt3(const float4* __restrict__ x, const float4* __restrict__ wqkv,
                     const float4* __restrict__ fcw)
{
    int i = blockIdx.x * blockDim.x + threadIdx.x;
    const float4* src;
    uint2* dst;
    int j;
    if (i < N_A4) {
        src = x;    dst = (uint2*)g_Ah; j = i;
    } else if (i < 2 * N_A4) {
        src = wqkv; dst = (uint2*)g_Bh; j = i - N_A4;
    } else if (i < 2 * N_A4 + N_W4) {
        src = fcw;  dst = (uint2*)g_Wh; j = i - 2 * N_A4;
    } else return;

    float4 v = src[j];
    uint2 H;
    H.x = pkh2(v.x, v.y);  H.y = pkh2(v.z, v.w);
    dst[j] = H;
}

// ---------------------------------------------------------------------------
#define LDSM4(R0,R1,R2,R3,addr) \
    asm volatile("ldmatrix.sync.aligned.m8n8.x4.shared.b16 {%0,%1,%2,%3}, [%4];" \
        : "=r"(R0),"=r"(R1),"=r"(R2),"=r"(R3) : "r"(addr))
#define LDSM4T(R0,R1,R2,R3,addr) \
    asm volatile("ldmatrix.sync.aligned.m8n8.x4.trans.shared.b16 {%0,%1,%2,%3}, [%4];" \
        : "=r"(R0),"=r"(R1),"=r"(R2),"=r"(R3) : "r"(addr))
#define CPASYNC16(dst, src) \
    asm volatile("cp.async.cg.shared.global [%0], [%1], 16;" :: "r"(dst), "l"(src))
#define CPCOMMIT() asm volatile("cp.async.commit_group;")
#define CPWAIT(n)  asm volatile("cp.async.wait_group %0;" :: "n"(n))

__device__ __forceinline__ void mma16816(float* c, const uint32_t* a,
                                         uint32_t b0, uint32_t b1)
{
    asm volatile(
        "mma.sync.aligned.m16n8k16.row.col.f32.f16.f16.f32 "
        "{%0,%1,%2,%3}, {%4,%5,%6,%7}, {%8,%9}, {%0,%1,%2,%3};"
        : "+f"(c[0]), "+f"(c[1]), "+f"(c[2]), "+f"(c[3])
        : "r"(a[0]), "r"(a[1]), "r"(a[2]), "r"(a[3]), "r"(b0), "r"(b1));
}

__device__ __forceinline__ uint32_t sw128(uint32_t off) {
    return off ^ ((off >> 3) & 0x70);
}

// ---------------------------------------------------------------------------
// HMMA fp16 single-term GEMM (NT): C = A @ B^T (+bias).
// CTA 64x128, 128 threads (warp 32x64), BK=64, 2-stage, 4 CTAs/SM.
// Stage: A 8K | B 16K = 24KB.
// ---------------------------------------------------------------------------
#define G_A 0
#define G_B 8192
#define G_STAGE 24576

template<bool SPLIT>
__global__ __launch_bounds__(128, 4)
void gemm_hmma(const __half* __restrict__ A, const __half* __restrict__ B,
               const float* __restrict__ bias, float* __restrict__ C,
               __half* __restrict__ Ch, int N, int K)
{
    extern __shared__ __align__(1024) char smem[];   // 2 x 24KB stages
    const int tid  = threadIdx.x;
    const int wid  = tid >> 5;
    const int lane = tid & 31;
    const int bm   = blockIdx.y * 64;
    const int bn   = blockIdx.x * 128;
    const int wm   = (wid & 1) * 32;
    const int wn   = (wid >> 1) * 64;

    const uint32_t smem_u = (uint32_t)__cvta_generic_to_shared(smem);

    float acc[2][8][4];
#pragma unroll
    for (int i = 0; i < 2; i++)
#pragma unroll
        for (int j = 0; j < 8; j++)
#pragma unroll
            for (int q = 0; q < 4; q++) acc[i][j][q] = 0.f;

    auto load_chunk = [&](int buf, int kc) {
        const int k0 = kc * 64;
        const uint32_t base = smem_u + buf * G_STAGE;
#pragma unroll
        for (int j = 0; j < 4; j++) {
            const int slot = j * 128 + tid;
            const int row = slot >> 3, sl = slot & 7;
            uint32_t off = sw128((uint32_t)(row * 128 + sl * 16));
            CPASYNC16(base + G_A + off, A + (size_t)(bm + row) * K + k0 + sl * 8);
        }
#pragma unroll
        for (int j = 0; j < 8; j++) {
            const int slot = j * 128 + tid;
            const int row = slot >> 3, sl = slot & 7;
            uint32_t off = sw128((uint32_t)(row * 128 + sl * 16));
            CPASYNC16(base + G_B + off, B + (size_t)(bn + row) * K + k0 + sl * 8);
        }
        CPCOMMIT();
    };

    const int NC = K / 64;
    load_chunk(0, 0);
    load_chunk(1, 1);

    const int lrow = lane & 15;
    const int lhi  = lane >> 4;

    for (int c = 0; c < NC; c++) {
        if (c == NC - 1) { CPWAIT(0); } else { CPWAIT(1); }
        __syncthreads();
        const uint32_t b = smem_u + (c & 1) * G_STAGE;

#pragma unroll
        for (int ks = 0; ks < 4; ks++) {
            uint32_t ah[2][4];
#pragma unroll
            for (int mi = 0; mi < 2; mi++) {
                const int row = wm + mi * 16 + lrow;
                uint32_t off = sw128((uint32_t)(row * 128 + (ks * 2 + lhi) * 16));
                LDSM4(ah[mi][0], ah[mi][1], ah[mi][2], ah[mi][3], b + G_A + off);
            }
#pragma unroll
            for (int np = 0; np < 4; np++) {
                uint32_t bh[4];
                const int row = wn + np * 16 + lrow;
                uint32_t off = sw128((uint32_t)(row * 128 + (ks * 2 + lhi) * 16));
                LDSM4(bh[0], bh[1], bh[2], bh[3], b + G_B + off);
#pragma unroll
                for (int mi = 0; mi < 2; mi++)
#pragma unroll
                    for (int hf = 0; hf < 2; hf++)
                        mma16816(acc[mi][np * 2 + hf], ah[mi], bh[hf], bh[2 + hf]);
            }
        }
        __syncthreads();
        if (c + 2 < NC) load_chunk(c & 1, c + 2);
    }

#pragma unroll
    for (int mi = 0; mi < 2; mi++) {
        const int m0 = bm + wm + mi * 16 + (lane >> 2);
#pragma unroll
        for (int nj = 0; nj < 8; nj++) {
            const int n0 = bn + wn + nj * 8 + (lane & 3) * 2;
#pragma unroll
            for (int hh = 0; hh < 2; hh++) {
                const int m = m0 + hh * 8;
                float v0 = acc[mi][nj][hh * 2 + 0];
                float v1 = acc[mi][nj][hh * 2 + 1];
                if (SPLIT) {
                    *(uint32_t*)(Ch + (size_t)m * N + n0) = pkh2(v0, v1);
                } else {
                    float2 v;
                    v.x = v0 + bias[n0];
                    v.y = v1 + bias[n0 + 1];
                    *(float2*)(C + (size_t)m * N + n0) = v;
                }
            }
        }
    }
}

// ---------------------------------------------------------------------------
// Flash attention, fp16 single-term scores, P kept hi+lo for PV.
// CTA = 128 threads (4 warps), 64 queries per (b,h,qt). 3 CTAs/SM.
// Q tile 8KB; KV chunk: k1h 8K | k2h 8K | vh 8K = 24KB, double-buffered.
// ---------------------------------------------------------------------------
#define A_OFF_KV 8192
#define A_OFF_KM 57344              // 8192 + 2*24576
#define A_OFF_MK 57856
#define A_SMEM   58368

__global__ __launch_bounds__(128, 3)
void attn_flash(const int* __restrict__ mask, const int* __restrict__ qmask,
                const float* __restrict__ shiftp, const float* __restrict__ biasp)
{
    extern __shared__ __align__(1024) char sm8[];
    const int tid  = threadIdx.x;
    const int lane = tid & 31;
    const int w    = tid >> 5;
    const int qt = blockIdx.x, h = blockIdx.y, b = blockIdx.z;
    const int lrow = lane & 15, lhi = lane >> 4;
    const int g = lane >> 2, t4 = lane & 3;

    const uint32_t su  = (uint32_t)__cvta_generic_to_shared(sm8);
    const uint32_t uKV = su + A_OFF_KV;
    char* sKm8 = sm8 + A_OFF_KM;
    char* sMk8 = sm8 + A_OFF_MK;

    const float shiftv = shiftp[0];
    const float biasv  = biasp[0];
    const size_t rowb  = (size_t)b * SEQ;

    for (int i = tid; i < 512; i += 128) {
        sKm8[i] = (char)qmask[rowb + i];
        sMk8[i] = (char)mask [rowb + i];
    }

    // Q tile (fp16)
#pragma unroll
    for (int j = 0; j < 4; j++) {
        const int slot = j * 128 + tid;
        const int row = slot >> 3, sl = slot & 7;
        CPASYNC16(su + sw128((uint32_t)(row * 128 + sl * 16)),
                  g_Qh + (rowb + qt * 64 + row) * 4096 + h * 64 + sl * 8);
    }
    CPCOMMIT();

    // chunk loader: k1h, k2h, vh
    auto ldKV = [&](int buf, int kt) {
        const uint32_t base = uKV + buf * 24576;
#pragma unroll
        for (int t = 0; t < 3; t++) {
            const int colb = (t + 1) * 1024 + h * 64;
#pragma unroll
            for (int j = 0; j < 4; j++) {
                const int slot = j * 128 + tid;
                const int row = slot >> 3, sl = slot & 7;
                CPASYNC16(base + t * 8192 + sw128((uint32_t)(row * 128 + sl * 16)),
                          g_Qh + (rowb + kt * 64 + row) * 4096 + colb + sl * 8);
            }
        }
        CPCOMMIT();
    };

    ldKV(0, 0);
    ldKV(1, 1);

    CPWAIT(2);                  // Q landed
    __syncthreads();

    uint32_t qh[4][4];
#pragma unroll
    for (int ks = 0; ks < 4; ks++) {
        uint32_t off = sw128((uint32_t)((w * 16 + lrow) * 128 + (ks * 2 + lhi) * 16));
        LDSM4(qh[ks][0], qh[ks][1], qh[ks][2], qh[ks][3], su + off);
    }

    char  qmv[2];
    float qgf[2];
#pragma unroll
    for (int hf = 0; hf < 2; hf++) {
        const int qr = qt * 64 + w * 16 + g + hf * 8;
        qmv[hf] = sKm8[qr];
        qgf[hf] = (float)qr;
    }

    float o[8][4];
#pragma unroll
    for (int d = 0; d < 8; d++)
#pragma unroll
        for (int q = 0; q < 4; q++) o[d][q] = 0.f;
    float mx[2] = {-1e30f, -1e30f};
    float sum[2] = {0.f, 0.f};

    for (int kt = 0; kt < 8; kt++) {
        if (kt == 7) { CPWAIT(0); } else { CPWAIT(1); }
        __syncthreads();
        const uint32_t kb = uKV + (kt & 1) * 24576;

        // ---- phase 1: scores for all 64 keys of this chunk ----
        float sv[4][2][2][2];               // [kp][nf][e][hf]
        float cmax[2] = {-1e30f, -1e30f};
#pragma unroll
        for (int kp = 0; kp < 4; kp++) {
            float a1[2][4], a2[2][4];
#pragma unroll
            for (int nf = 0; nf < 2; nf++)
#pragma unroll
                for (int q = 0; q < 4; q++) { a1[nf][q] = 0.f; a2[nf][q] = 0.f; }

#pragma unroll
            for (int ks = 0; ks < 4; ks++) {
                uint32_t k1h[4], k2h[4];
                uint32_t off = sw128((uint32_t)((kp * 16 + lrow) * 128 + (ks * 2 + lhi) * 16));
                LDSM4(k1h[0], k1h[1], k1h[2], k1h[3], kb + off);
                LDSM4(k2h[0], k2h[1], k2h[2], k2h[3], kb + 8192 + off);
#pragma unroll
                for (int nf = 0; nf < 2; nf++) {
                    mma16816(a1[nf], qh[ks], k1h[nf], k1h[2 + nf]);
                    mma16816(a2[nf], qh[ks], k2h[nf], k2h[2 + nf]);
                }
            }

#pragma unroll
            for (int nf = 0; nf < 2; nf++)
#pragma unroll
                for (int e = 0; e < 2; e++) {
                    const int kg = kt * 64 + kp * 16 + nf * 8 + t4 * 2 + e;
                    const char km = sKm8[kg];
                    const char mk = sMk8[kg];
                    const float kgf = (float)kg;
#pragma unroll
                    for (int hf = 0; hf < 2; hf++) {
                        const float v = (qmv[hf] == km) ? a1[nf][hf * 2 + e]
                                                        : a2[nf][hf * 2 + e];
                        const float dd = qgf[hf] - kgf;
                        float s = v * 0.125f - (shiftv * dd * dd + biasv);
                        if (!mk) s = -1e30f;
                        sv[kp][nf][e][hf] = s;
                        cmax[hf] = fmaxf(cmax[hf], s);
                    }
                }
        }

        // ---- phase 2: one softmax update per 64-key chunk ----
#pragma unroll
        for (int hf = 0; hf < 2; hf++) {
            cmax[hf] = fmaxf(cmax[hf], __shfl_xor_sync(0xffffffffu, cmax[hf], 1));
            cmax[hf] = fmaxf(cmax[hf], __shfl_xor_sync(0xffffffffu, cmax[hf], 2));
        }
        float corr[2];
#pragma unroll
        for (int hf = 0; hf < 2; hf++) {
            const float nm = fmaxf(mx[hf], cmax[hf]);
            corr[hf] = __expf(mx[hf] - nm);
            mx[hf] = nm;
            sum[hf] *= corr[hf];
        }
#pragma unroll
        for (int d = 0; d < 8; d++) {
            o[d][0] *= corr[0]; o[d][1] *= corr[0];
            o[d][2] *= corr[1]; o[d][3] *= corr[1];
        }

        // ---- phase 3: exp + pack P fragments (fp16 hi/lo) ----
        uint32_t pH[4][4], pL[4][4];
#pragma unroll
        for (int kp = 0; kp < 4; kp++)
#pragma unroll
            for (int nf = 0; nf < 2; nf++)
#pragma unroll
                for (int hf = 0; hf < 2; hf++) {
                    const float p0 = __expf(sv[kp][nf][0][hf] - mx[hf]);
                    const float p1 = __expf(sv[kp][nf][1][hf] - mx[hf]);
                    sum[hf] += p0 + p1;
                    const float h0 = __half2float(__float2half(p0));
                    const float h1 = __half2float(__float2half(p1));
                    const int idx = nf * 2 + hf;
                    pH[kp][idx] = pkh2(p0, p1);
                    pL[kp][idx] = pkh2(p0 - h0, p1 - h1);
                }

        // ---- phase 4: P @ Vh over the 64-key chunk ----
        const int quad = lane >> 3, r = lane & 7;
#pragma unroll
        for (int dblk = 0; dblk < 4; dblk++) {
#pragma unroll
            for (int kp = 0; kp < 4; kp++) {
                uint32_t vh[4];
                uint32_t boff = sw128((uint32_t)((kp * 16 + (quad & 1) * 8 + r) * 128
                                                 + dblk * 32 + (quad >> 1) * 16));
                LDSM4T(vh[0], vh[1], vh[2], vh[3], kb + 16384 + boff);
#pragma unroll
                for (int nf = 0; nf < 2; nf++) {
                    mma16816(o[dblk * 2 + nf], pH[kp], vh[nf * 2], vh[nf * 2 + 1]);
                    mma16816(o[dblk * 2 + nf], pL[kp], vh[nf * 2], vh[nf * 2 + 1]);
                }
            }
        }
        __syncthreads();
        if (kt + 2 < 8) ldKV(kt & 1, kt + 2);
    }

    // finalize: normalize, write fp16 att into g_Ah
    float inv[2];
#pragma unroll
    for (int hf = 0; hf < 2; hf++) {
        float s = sum[hf];
        s += __shfl_xor_sync(0xffffffffu, s, 1);
        s += __shfl_xor_sync(0xffffffffu, s, 2);
        inv[hf] = 1.0f / s;
    }
#pragma unroll
    for (int d = 0; d < 8; d++) {
        const int col = h * 64 + (d >> 1) * 16 + (d & 1) * 8 + t4 * 2;
#pragma unroll
        for (int hf = 0; hf < 2; hf++) {
            const size_t row = rowb + qt * 64 + w * 16 + g + hf * 8;
            const float v0 = o[d][hf * 2 + 0] * inv[hf];
            const float v1 = o[d][hf * 2 + 1] * inv[hf];
            *(uint32_t*)(g_Ah + row * DMODEL + col) = pkh2(v0, v1);
        }
    }
}

// ---------------------------------------------------------------------------
extern "C" void kernel_launch(void* const* d_in, const int* in_sizes, int n_in,
                              void* d_out, int out_size)
{
    const float* x     = (const float*)d_in[0];
    const int*   mask  = (const int*)  d_in[1];
    const int*   qmask = (const int*)  d_in[2];
    const float* Wqkv  = (const float*)d_in[3];
    const float* fc_w  = (const float*)d_in[4];
    const float* fc_b  = (const float*)d_in[5];
    const float* shift = (const float*)d_in[6];
    const float* bias  = (const float*)d_in[7];
    float* out = (float*)d_out;

    __half *qh, *ah, *bh, *wh;
    cudaGetSymbolAddress((void**)&qh, g_Qh);
    cudaGetSymbolAddress((void**)&ah, g_Ah);
    cudaGetSymbolAddress((void**)&bh, g_Bh);
    cudaGetSymbolAddress((void**)&wh, g_Wh);

    cudaFuncSetAttribute(gemm_hmma<true>,  cudaFuncAttributeMaxDynamicSharedMemorySize, 2 * G_STAGE);
    cudaFuncSetAttribute(gemm_hmma<false>, cudaFuncAttributeMaxDynamicSharedMemorySize, 2 * G_STAGE);
    cudaFuncSetAttribute(attn_flash, cudaFuncAttributeMaxDynamicSharedMemorySize, A_SMEM);

    // 1) fp16 conversions: x -> Ah, Wqkv -> Bh, fc_w -> Wh
    {
        const int total = 2 * N_A4 + N_W4;
        cvt3<<<(total + 255) / 256, 256>>>((const float4*)x, (const float4*)Wqkv,
                                           (const float4*)fc_w);
    }

    // 2) qkv = x @ Wqkv^T, fp16 epilogue
    {
        dim3 grid(4 * DMODEL / 128, MROWS / 64);    // (32, 64)
        gemm_hmma<true><<<grid, 128, 2 * G_STAGE>>>(ah, bh, nullptr, nullptr,
                                                    qh, 4 * DMODEL, DMODEL);
    }

    // 3) flash attention, writes fp16 att into g_Ah
    {
        dim3 grid(SEQ / 64, NHEAD, BATCH);          // (8, 16, 8)
        attn_flash<<<grid, 128, A_SMEM>>>(mask, qmask, shift, bias);
    }

    // 4) out = att @ fc_w^T + fc_b (fp32 epilogue)
    {
        dim3 grid(DMODEL / 128, MROWS / 64);        // (8, 64)
        gemm_hmma<false><<<grid, 128, 2 * G_STAGE>>>(ah, wh, fc_b, out,
                                                     nullptr, DMODEL, DMODEL);
    }
}

// round 16
// speedup vs baseline: 2.4895x; 1.0235x over previous
#include <cuda_runtime.h>
#include <cuda_fp16.h>
#include <math.h>
#include <stdint.h>

#define BATCH 8
#define SEQ   512
#define DMODEL 1024
#define NHEAD 16
#define DHEAD 64
#define MROWS (BATCH*SEQ)        // 4096

// ---------------- scratch (no cudaMalloc allowed) ----------------
__device__ __half g_Qh[(size_t)MROWS * 4 * DMODEL];  // qkv fp16 (32MB)
__device__ __half g_Ah[(size_t)MROWS * DMODEL];      // x fp16 / att fp16
__device__ __half g_Bh[(size_t)MROWS * DMODEL];      // Wqkv fp16
__device__ __half g_Wh[(size_t)DMODEL * DMODEL];     // fc_w fp16

// ---------------------------------------------------------------------------
__device__ __forceinline__ uint32_t pkh2(float a, float b) {
    __half2 t = __floats2half2_rn(a, b);
    return *reinterpret_cast<uint32_t*>(&t);
}

#define N_A4 (MROWS * DMODEL / 4)
#define N_W4 (DMODEL * DMODEL / 4)
__global__ void cvt3(const float4* __restrict__ x, const float4* __restrict__ wqkv,
                     const float4* __restrict__ fcw)
{
    int i = blockIdx.x * blockDim.x + threadIdx.x;
    const float4* src;
    uint2* dst;
    int j;
    if (i < N_A4) {
        src = x;    dst = (uint2*)g_Ah; j = i;
    } else if (i < 2 * N_A4) {
        src = wqkv; dst = (uint2*)g_Bh; j = i - N_A4;
    } else if (i < 2 * N_A4 + N_W4) {
        src = fcw;  dst = (uint2*)g_Wh; j = i - 2 * N_A4;
    } else return;

    float4 v = src[j];
    uint2 H;
    H.x = pkh2(v.x, v.y);  H.y = pkh2(v.z, v.w);
    dst[j] = H;
}

// ---------------------------------------------------------------------------
#define LDSM4(R0,R1,R2,R3,addr) \
    asm volatile("ldmatrix.sync.aligned.m8n8.x4.shared.b16 {%0,%1,%2,%3}, [%4];" \
        : "=r"(R0),"=r"(R1),"=r"(R2),"=r"(R3) : "r"(addr))
#define LDSM4T(R0,R1,R2,R3,addr) \
    asm volatile("ldmatrix.sync.aligned.m8n8.x4.trans.shared.b16 {%0,%1,%2,%3}, [%4];" \
        : "=r"(R0),"=r"(R1),"=r"(R2),"=r"(R3) : "r"(addr))
#define CPASYNC16(dst, src) \
    asm volatile("cp.async.cg.shared.global [%0], [%1], 16;" :: "r"(dst), "l"(src))
#define CPCOMMIT() asm volatile("cp.async.commit_group;")
#define CPWAIT(n)  asm volatile("cp.async.wait_group %0;" :: "n"(n))

__device__ __forceinline__ void mma16816(float* c, const uint32_t* a,
                                         uint32_t b0, uint32_t b1)
{
    asm volatile(
        "mma.sync.aligned.m16n8k16.row.col.f32.f16.f16.f32 "
        "{%0,%1,%2,%3}, {%4,%5,%6,%7}, {%8,%9}, {%0,%1,%2,%3};"
        : "+f"(c[0]), "+f"(c[1]), "+f"(c[2]), "+f"(c[3])
        : "r"(a[0]), "r"(a[1]), "r"(a[2]), "r"(a[3]), "r"(b0), "r"(b1));
}

__device__ __forceinline__ uint32_t sw128(uint32_t off) {
    return off ^ ((off >> 3) & 0x70);
}

// ---------------------------------------------------------------------------
// HMMA fp16 single-term GEMM (NT): C = A @ B^T (+bias).
// CTA 128x128, 256 threads (8 warps 4x2, warp 32x64), BK=64, 2-stage,
// 2 CTAs/SM.  Stage: A 16K | B 16K = 32KB.
// ---------------------------------------------------------------------------
#define G_A 0
#define G_B 16384
#define G_STAGE 32768

template<bool SPLIT>
__global__ __launch_bounds__(256, 2)
void gemm_hmma(const __half* __restrict__ A, const __half* __restrict__ B,
               const float* __restrict__ bias, float* __restrict__ C,
               __half* __restrict__ Ch, int N, int K)
{
    extern __shared__ __align__(1024) char smem[];   // 2 x 32KB stages
    const int tid  = threadIdx.x;
    const int wid  = tid >> 5;
    const int lane = tid & 31;
    const int bm   = blockIdx.y * 128;
    const int bn   = blockIdx.x * 128;
    const int wm   = (wid & 3) * 32;
    const int wn   = (wid >> 2) * 64;

    const uint32_t smem_u = (uint32_t)__cvta_generic_to_shared(smem);

    float acc[2][8][4];
#pragma unroll
    for (int i = 0; i < 2; i++)
#pragma unroll
        for (int j = 0; j < 8; j++)
#pragma unroll
            for (int q = 0; q < 4; q++) acc[i][j][q] = 0.f;

    auto load_chunk = [&](int buf, int kc) {
        const int k0 = kc * 64;
        const uint32_t base = smem_u + buf * G_STAGE;
#pragma unroll
        for (int j = 0; j < 4; j++) {
            const int slot = j * 256 + tid;          // 1024 slots each tensor
            const int row = slot >> 3, sl = slot & 7;
            uint32_t off = sw128((uint32_t)(row * 128 + sl * 16));
            CPASYNC16(base + G_A + off, A + (size_t)(bm + row) * K + k0 + sl * 8);
            CPASYNC16(base + G_B + off, B + (size_t)(bn + row) * K + k0 + sl * 8);
        }
        CPCOMMIT();
    };

    const int NC = K / 64;
    load_chunk(0, 0);
    load_chunk(1, 1);

    const int lrow = lane & 15;
    const int lhi  = lane >> 4;

    for (int c = 0; c < NC; c++) {
        if (c == NC - 1) { CPWAIT(0); } else { CPWAIT(1); }
        __syncthreads();
        const uint32_t b = smem_u + (c & 1) * G_STAGE;

#pragma unroll
        for (int ks = 0; ks < 4; ks++) {
            uint32_t ah[2][4];
#pragma unroll
            for (int mi = 0; mi < 2; mi++) {
                const int row = wm + mi * 16 + lrow;
                uint32_t off = sw128((uint32_t)(row * 128 + (ks * 2 + lhi) * 16));
                LDSM4(ah[mi][0], ah[mi][1], ah[mi][2], ah[mi][3], b + G_A + off);
            }
#pragma unroll
            for (int np = 0; np < 4; np++) {
                uint32_t bh[4];
                const int row = wn + np * 16 + lrow;
                uint32_t off = sw128((uint32_t)(row * 128 + (ks * 2 + lhi) * 16));
                LDSM4(bh[0], bh[1], bh[2], bh[3], b + G_B + off);
#pragma unroll
                for (int mi = 0; mi < 2; mi++)
#pragma unroll
                    for (int hf = 0; hf < 2; hf++)
                        mma16816(acc[mi][np * 2 + hf], ah[mi], bh[hf], bh[2 + hf]);
            }
        }
        __syncthreads();
        if (c + 2 < NC) load_chunk(c & 1, c + 2);
    }

#pragma unroll
    for (int mi = 0; mi < 2; mi++) {
        const int m0 = bm + wm + mi * 16 + (lane >> 2);
#pragma unroll
        for (int nj = 0; nj < 8; nj++) {
            const int n0 = bn + wn + nj * 8 + (lane & 3) * 2;
#pragma unroll
            for (int hh = 0; hh < 2; hh++) {
                const int m = m0 + hh * 8;
                float v0 = acc[mi][nj][hh * 2 + 0];
                float v1 = acc[mi][nj][hh * 2 + 1];
                if (SPLIT) {
                    *(uint32_t*)(Ch + (size_t)m * N + n0) = pkh2(v0, v1);
                } else {
                    float2 v;
                    v.x = v0 + bias[n0];
                    v.y = v1 + bias[n0 + 1];
                    *(float2*)(C + (size_t)m * N + n0) = v;
                }
            }
        }
    }
}

// ---------------------------------------------------------------------------
// Flash attention, fp16 single-term scores, P kept hi+lo for PV. (R15 proven)
// CTA = 128 threads (4 warps), 64 queries per (b,h,qt). 3 CTAs/SM.
// ---------------------------------------------------------------------------
#define A_OFF_KV 8192
#define A_OFF_KM 57344              // 8192 + 2*24576
#define A_OFF_MK 57856
#define A_SMEM   58368

__global__ __launch_bounds__(128, 3)
void attn_flash(const int* __restrict__ mask, const int* __restrict__ qmask,
                const float* __restrict__ shiftp, const float* __restrict__ biasp)
{
    extern __shared__ __align__(1024) char sm8[];
    const int tid  = threadIdx.x;
    const int lane = tid & 31;
    const int w    = tid >> 5;
    const int qt = blockIdx.x, h = blockIdx.y, b = blockIdx.z;
    const int lrow = lane & 15, lhi = lane >> 4;
    const int g = lane >> 2, t4 = lane & 3;

    const uint32_t su  = (uint32_t)__cvta_generic_to_shared(sm8);
    const uint32_t uKV = su + A_OFF_KV;
    char* sKm8 = sm8 + A_OFF_KM;
    char* sMk8 = sm8 + A_OFF_MK;

    const float shiftv = shiftp[0];
    const float biasv  = biasp[0];
    const size_t rowb  = (size_t)b * SEQ;

    for (int i = tid; i < 512; i += 128) {
        sKm8[i] = (char)qmask[rowb + i];
        sMk8[i] = (char)mask [rowb + i];
    }

    // Q tile (fp16)
#pragma unroll
    for (int j = 0; j < 4; j++) {
        const int slot = j * 128 + tid;
        const int row = slot >> 3, sl = slot & 7;
        CPASYNC16(su + sw128((uint32_t)(row * 128 + sl * 16)),
                  g_Qh + (rowb + qt * 64 + row) * 4096 + h * 64 + sl * 8);
    }
    CPCOMMIT();

    auto ldKV = [&](int buf, int kt) {
        const uint32_t base = uKV + buf * 24576;
#pragma unroll
        for (int t = 0; t < 3; t++) {
            const int colb = (t + 1) * 1024 + h * 64;
#pragma unroll
            for (int j = 0; j < 4; j++) {
                const int slot = j * 128 + tid;
                const int row = slot >> 3, sl = slot & 7;
                CPASYNC16(base + t * 8192 + sw128((uint32_t)(row * 128 + sl * 16)),
                          g_Qh + (rowb + kt * 64 + row) * 4096 + colb + sl * 8);
            }
        }
        CPCOMMIT();
    };

    ldKV(0, 0);
    ldKV(1, 1);

    CPWAIT(2);                  // Q landed
    __syncthreads();

    uint32_t qh[4][4];
#pragma unroll
    for (int ks = 0; ks < 4; ks++) {
        uint32_t off = sw128((uint32_t)((w * 16 + lrow) * 128 + (ks * 2 + lhi) * 16));
        LDSM4(qh[ks][0], qh[ks][1], qh[ks][2], qh[ks][3], su + off);
    }

    char  qmv[2];
    float qgf[2];
#pragma unroll
    for (int hf = 0; hf < 2; hf++) {
        const int qr = qt * 64 + w * 16 + g + hf * 8;
        qmv[hf] = sKm8[qr];
        qgf[hf] = (float)qr;
    }

    float o[8][4];
#pragma unroll
    for (int d = 0; d < 8; d++)
#pragma unroll
        for (int q = 0; q < 4; q++) o[d][q] = 0.f;
    float mx[2] = {-1e30f, -1e30f};
    float sum[2] = {0.f, 0.f};

    for (int kt = 0; kt < 8; kt++) {
        if (kt == 7) { CPWAIT(0); } else { CPWAIT(1); }
        __syncthreads();
        const uint32_t kb = uKV + (kt & 1) * 24576;

        // ---- phase 1: scores for all 64 keys of this chunk ----
        float sv[4][2][2][2];               // [kp][nf][e][hf]
        float cmax[2] = {-1e30f, -1e30f};
#pragma unroll
        for (int kp = 0; kp < 4; kp++) {
            float a1[2][4], a2[2][4];
#pragma unroll
            for (int nf = 0; nf < 2; nf++)
#pragma unroll
                for (int q = 0; q < 4; q++) { a1[nf][q] = 0.f; a2[nf][q] = 0.f; }

#pragma unroll
            for (int ks = 0; ks < 4; ks++) {
                uint32_t k1h[4], k2h[4];
                uint32_t off = sw128((uint32_t)((kp * 16 + lrow) * 128 + (ks * 2 + lhi) * 16));
                LDSM4(k1h[0], k1h[1], k1h[2], k1h[3], kb + off);
                LDSM4(k2h[0], k2h[1], k2h[2], k2h[3], kb + 8192 + off);
#pragma unroll
                for (int nf = 0; nf < 2; nf++) {
                    mma16816(a1[nf], qh[ks], k1h[nf], k1h[2 + nf]);
                    mma16816(a2[nf], qh[ks], k2h[nf], k2h[2 + nf]);
                }
            }

#pragma unroll
            for (int nf = 0; nf < 2; nf++)
#pragma unroll
                for (int e = 0; e < 2; e++) {
                    const int kg = kt * 64 + kp * 16 + nf * 8 + t4 * 2 + e;
                    const char km = sKm8[kg];
                    const char mk = sMk8[kg];
                    const float kgf = (float)kg;
#pragma unroll
                    for (int hf = 0; hf < 2; hf++) {
                        const float v = (qmv[hf] == km) ? a1[nf][hf * 2 + e]
                                                        : a2[nf][hf * 2 + e];
                        const float dd = qgf[hf] - kgf;
                        float s = v * 0.125f - (shiftv * dd * dd + biasv);
                        if (!mk) s = -1e30f;
                        sv[kp][nf][e][hf] = s;
                        cmax[hf] = fmaxf(cmax[hf], s);
                    }
                }
        }

        // ---- phase 2: one softmax update per 64-key chunk ----
#pragma unroll
        for (int hf = 0; hf < 2; hf++) {
            cmax[hf] = fmaxf(cmax[hf], __shfl_xor_sync(0xffffffffu, cmax[hf], 1));
            cmax[hf] = fmaxf(cmax[hf], __shfl_xor_sync(0xffffffffu, cmax[hf], 2));
        }
        float corr[2];
#pragma unroll
        for (int hf = 0; hf < 2; hf++) {
            const float nm = fmaxf(mx[hf], cmax[hf]);
            corr[hf] = __expf(mx[hf] - nm);
            mx[hf] = nm;
            sum[hf] *= corr[hf];
        }
#pragma unroll
        for (int d = 0; d < 8; d++) {
            o[d][0] *= corr[0]; o[d][1] *= corr[0];
            o[d][2] *= corr[1]; o[d][3] *= corr[1];
        }

        // ---- phase 3: exp + pack P fragments (fp16 hi/lo) ----
        uint32_t pH[4][4], pL[4][4];
#pragma unroll
        for (int kp = 0; kp < 4; kp++)
#pragma unroll
            for (int nf = 0; nf < 2; nf++)
#pragma unroll
                for (int hf = 0; hf < 2; hf++) {
                    const float p0 = __expf(sv[kp][nf][0][hf] - mx[hf]);
                    const float p1 = __expf(sv[kp][nf][1][hf] - mx[hf]);
                    sum[hf] += p0 + p1;
                    const float h0 = __half2float(__float2half(p0));
                    const float h1 = __half2float(__float2half(p1));
                    const int idx = nf * 2 + hf;
                    pH[kp][idx] = pkh2(p0, p1);
                    pL[kp][idx] = pkh2(p0 - h0, p1 - h1);
                }

        // ---- phase 4: P @ Vh over the 64-key chunk ----
        const int quad = lane >> 3, r = lane & 7;
#pragma unroll
        for (int dblk = 0; dblk < 4; dblk++) {
#pragma unroll
            for (int kp = 0; kp < 4; kp++) {
                uint32_t vh[4];
                uint32_t boff = sw128((uint32_t)((kp * 16 + (quad & 1) * 8 + r) * 128
                                                 + dblk * 32 + (quad >> 1) * 16));
                LDSM4T(vh[0], vh[1], vh[2], vh[3], kb + 16384 + boff);
#pragma unroll
                for (int nf = 0; nf < 2; nf++) {
                    mma16816(o[dblk * 2 + nf], pH[kp], vh[nf * 2], vh[nf * 2 + 1]);
                    mma16816(o[dblk * 2 + nf], pL[kp], vh[nf * 2], vh[nf * 2 + 1]);
                }
            }
        }
        __syncthreads();
        if (kt + 2 < 8) ldKV(kt & 1, kt + 2);
    }

    // finalize: normalize, write fp16 att into g_Ah
    float inv[2];
#pragma unroll
    for (int hf = 0; hf < 2; hf++) {
        float s = sum[hf];
        s += __shfl_xor_sync(0xffffffffu, s, 1);
        s += __shfl_xor_sync(0xffffffffu, s, 2);
        inv[hf] = 1.0f / s;
    }
#pragma unroll
    for (int d = 0; d < 8; d++) {
        const int col = h * 64 + (d >> 1) * 16 + (d & 1) * 8 + t4 * 2;
#pragma unroll
        for (int hf = 0; hf < 2; hf++) {
            const size_t row = rowb + qt * 64 + w * 16 + g + hf * 8;
            const float v0 = o[d][hf * 2 + 0] * inv[hf];
            const float v1 = o[d][hf * 2 + 1] * inv[hf];
            *(uint32_t*)(g_Ah + row * DMODEL + col) = pkh2(v0, v1);
        }
    }
}

// ---------------------------------------------------------------------------
extern "C" void kernel_launch(void* const* d_in, const int* in_sizes, int n_in,
                              void* d_out, int out_size)
{
    const float* x     = (const float*)d_in[0];
    const int*   mask  = (const int*)  d_in[1];
    const int*   qmask = (const int*)  d_in[2];
    const float* Wqkv  = (const float*)d_in[3];
    const float* fc_w  = (const float*)d_in[4];
    const float* fc_b  = (const float*)d_in[5];
    const float* shift = (const float*)d_in[6];
    const float* bias  = (const float*)d_in[7];
    float* out = (float*)d_out;

    __half *qh, *ah, *bh, *wh;
    cudaGetSymbolAddress((void**)&qh, g_Qh);
    cudaGetSymbolAddress((void**)&ah, g_Ah);
    cudaGetSymbolAddress((void**)&bh, g_Bh);
    cudaGetSymbolAddress((void**)&wh, g_Wh);

    cudaFuncSetAttribute(gemm_hmma<true>,  cudaFuncAttributeMaxDynamicSharedMemorySize, 2 * G_STAGE);
    cudaFuncSetAttribute(gemm_hmma<false>, cudaFuncAttributeMaxDynamicSharedMemorySize, 2 * G_STAGE);
    cudaFuncSetAttribute(attn_flash, cudaFuncAttributeMaxDynamicSharedMemorySize, A_SMEM);

    // 1) fp16 conversions: x -> Ah, Wqkv -> Bh, fc_w -> Wh
    {
        const int total = 2 * N_A4 + N_W4;
        cvt3<<<(total + 255) / 256, 256>>>((const float4*)x, (const float4*)Wqkv,
                                           (const float4*)fc_w);
    }

    // 2) qkv = x @ Wqkv^T, fp16 epilogue
    {
        dim3 grid(4 * DMODEL / 128, MROWS / 128);   // (32, 32)
        gemm_hmma<true><<<grid, 256, 2 * G_STAGE>>>(ah, bh, nullptr, nullptr,
                                                    qh, 4 * DMODEL, DMODEL);
    }

    // 3) flash attention, writes fp16 att into g_Ah
    {
        dim3 grid(SEQ / 64, NHEAD, BATCH);          // (8, 16, 8)
        attn_flash<<<grid, 128, A_SMEM>>>(mask, qmask, shift, bias);
    }

    // 4) out = att @ fc_w^T + fc_b (fp32 epilogue)
    {
        dim3 grid(DMODEL / 128, MROWS / 128);       // (8, 32)
        gemm_hmma<false><<<grid, 256, 2 * G_STAGE>>>(ah, wh, fc_b, out,
                                                     nullptr, DMODEL, DMODEL);
    }
}

// round 17
// speedup vs baseline: 2.5429x; 1.0214x over previous
#include <cuda_runtime.h>
#include <cuda_fp16.h>
#include <math.h>
#include <stdint.h>

#define BATCH 8
#define SEQ   512
#define DMODEL 1024
#define NHEAD 16
#define DHEAD 64
#define MROWS (BATCH*SEQ)        // 4096

// ---------------- scratch (no cudaMalloc allowed) ----------------
__device__ __half g_Qh[(size_t)MROWS * 4 * DMODEL];  // qkv fp16 (32MB)
__device__ __half g_Ah[(size_t)MROWS * DMODEL];      // x fp16 / att fp16
__device__ __half g_Bh[(size_t)MROWS * DMODEL];      // Wqkv fp16
__device__ __half g_Wh[(size_t)DMODEL * DMODEL];     // fc_w fp16

// ---------------------------------------------------------------------------
__device__ __forceinline__ uint32_t pkh2(float a, float b) {
    __half2 t = __floats2half2_rn(a, b);
    return *reinterpret_cast<uint32_t*>(&t);
}

#define N_A4 (MROWS * DMODEL / 4)
#define N_W4 (DMODEL * DMODEL / 4)
__global__ void cvt3(const float4* __restrict__ x, const float4* __restrict__ wqkv,
                     const float4* __restrict__ fcw)
{
    int i = blockIdx.x * blockDim.x + threadIdx.x;
    const float4* src;
    uint2* dst;
    int j;
    if (i < N_A4) {
        src = x;    dst = (uint2*)g_Ah; j = i;
    } else if (i < 2 * N_A4) {
        src = wqkv; dst = (uint2*)g_Bh; j = i - N_A4;
    } else if (i < 2 * N_A4 + N_W4) {
        src = fcw;  dst = (uint2*)g_Wh; j = i - 2 * N_A4;
    } else return;

    float4 v = src[j];
    uint2 H;
    H.x = pkh2(v.x, v.y);  H.y = pkh2(v.z, v.w);
    dst[j] = H;
}

// ---------------------------------------------------------------------------
#define LDSM4(R0,R1,R2,R3,addr) \
    asm volatile("ldmatrix.sync.aligned.m8n8.x4.shared.b16 {%0,%1,%2,%3}, [%4];" \
        : "=r"(R0),"=r"(R1),"=r"(R2),"=r"(R3) : "r"(addr))
#define LDSM4T(R0,R1,R2,R3,addr) \
    asm volatile("ldmatrix.sync.aligned.m8n8.x4.trans.shared.b16 {%0,%1,%2,%3}, [%4];" \
        : "=r"(R0),"=r"(R1),"=r"(R2),"=r"(R3) : "r"(addr))
#define CPASYNC16(dst, src) \
    asm volatile("cp.async.cg.shared.global [%0], [%1], 16;" :: "r"(dst), "l"(src))
#define CPCOMMIT() asm volatile("cp.async.commit_group;")
#define CPWAIT(n)  asm volatile("cp.async.wait_group %0;" :: "n"(n))

__device__ __forceinline__ void mma16816(float* c, const uint32_t* a,
                                         uint32_t b0, uint32_t b1)
{
    asm volatile(
        "mma.sync.aligned.m16n8k16.row.col.f32.f16.f16.f32 "
        "{%0,%1,%2,%3}, {%4,%5,%6,%7}, {%8,%9}, {%0,%1,%2,%3};"
        : "+f"(c[0]), "+f"(c[1]), "+f"(c[2]), "+f"(c[3])
        : "r"(a[0]), "r"(a[1]), "r"(a[2]), "r"(a[3]), "r"(b0), "r"(b1));
}

__device__ __forceinline__ uint32_t sw128(uint32_t off) {
    return off ^ ((off >> 3) & 0x70);
}

// ---------------------------------------------------------------------------
// HMMA fp16 single-term GEMM (NT): C = A @ B^T (+bias).  (R16 proven)
// CTA 128x128, 256 threads (8 warps 4x2, warp 32x64), BK=64, 2-stage,
// 2 CTAs/SM.  Stage: A 16K | B 16K = 32KB.
// ---------------------------------------------------------------------------
#define G_A 0
#define G_B 16384
#define G_STAGE 32768

template<bool SPLIT>
__global__ __launch_bounds__(256, 2)
void gemm_hmma(const __half* __restrict__ A, const __half* __restrict__ B,
               const float* __restrict__ bias, float* __restrict__ C,
               __half* __restrict__ Ch, int N, int K)
{
    extern __shared__ __align__(1024) char smem[];
    const int tid  = threadIdx.x;
    const int wid  = tid >> 5;
    const int lane = tid & 31;
    const int bm   = blockIdx.y * 128;
    const int bn   = blockIdx.x * 128;
    const int wm   = (wid & 3) * 32;
    const int wn   = (wid >> 2) * 64;

    const uint32_t smem_u = (uint32_t)__cvta_generic_to_shared(smem);

    float acc[2][8][4];
#pragma unroll
    for (int i = 0; i < 2; i++)
#pragma unroll
        for (int j = 0; j < 8; j++)
#pragma unroll
            for (int q = 0; q < 4; q++) acc[i][j][q] = 0.f;

    auto load_chunk = [&](int buf, int kc) {
        const int k0 = kc * 64;
        const uint32_t base = smem_u + buf * G_STAGE;
#pragma unroll
        for (int j = 0; j < 4; j++) {
            const int slot = j * 256 + tid;
            const int row = slot >> 3, sl = slot & 7;
            uint32_t off = sw128((uint32_t)(row * 128 + sl * 16));
            CPASYNC16(base + G_A + off, A + (size_t)(bm + row) * K + k0 + sl * 8);
            CPASYNC16(base + G_B + off, B + (size_t)(bn + row) * K + k0 + sl * 8);
        }
        CPCOMMIT();
    };

    const int NC = K / 64;
    load_chunk(0, 0);
    load_chunk(1, 1);

    const int lrow = lane & 15;
    const int lhi  = lane >> 4;

    for (int c = 0; c < NC; c++) {
        if (c == NC - 1) { CPWAIT(0); } else { CPWAIT(1); }
        __syncthreads();
        const uint32_t b = smem_u + (c & 1) * G_STAGE;

#pragma unroll
        for (int ks = 0; ks < 4; ks++) {
            uint32_t ah[2][4];
#pragma unroll
            for (int mi = 0; mi < 2; mi++) {
                const int row = wm + mi * 16 + lrow;
                uint32_t off = sw128((uint32_t)(row * 128 + (ks * 2 + lhi) * 16));
                LDSM4(ah[mi][0], ah[mi][1], ah[mi][2], ah[mi][3], b + G_A + off);
            }
#pragma unroll
            for (int np = 0; np < 4; np++) {
                uint32_t bh[4];
                const int row = wn + np * 16 + lrow;
                uint32_t off = sw128((uint32_t)(row * 128 + (ks * 2 + lhi) * 16));
                LDSM4(bh[0], bh[1], bh[2], bh[3], b + G_B + off);
#pragma unroll
                for (int mi = 0; mi < 2; mi++)
#pragma unroll
                    for (int hf = 0; hf < 2; hf++)
                        mma16816(acc[mi][np * 2 + hf], ah[mi], bh[hf], bh[2 + hf]);
            }
        }
        __syncthreads();
        if (c + 2 < NC) load_chunk(c & 1, c + 2);
    }

#pragma unroll
    for (int mi = 0; mi < 2; mi++) {
        const int m0 = bm + wm + mi * 16 + (lane >> 2);
#pragma unroll
        for (int nj = 0; nj < 8; nj++) {
            const int n0 = bn + wn + nj * 8 + (lane & 3) * 2;
#pragma unroll
            for (int hh = 0; hh < 2; hh++) {
                const int m = m0 + hh * 8;
                float v0 = acc[mi][nj][hh * 2 + 0];
                float v1 = acc[mi][nj][hh * 2 + 1];
                if (SPLIT) {
                    *(uint32_t*)(Ch + (size_t)m * N + n0) = pkh2(v0, v1);
                } else {
                    float2 v;
                    v.x = v0 + bias[n0];
                    v.y = v1 + bias[n0 + 1];
                    *(float2*)(C + (size_t)m * N + n0) = v;
                }
            }
        }
    }
}

// ---------------------------------------------------------------------------
// Flash attention, fp16 single-term scores AND single-term PV. 4 CTAs/SM.
// CTA = 128 threads (4 warps), 64 queries per (b,h,qt).
// smem: Q 8K | KV 2x24K | merged masks 512B = 57,856 B.
// ---------------------------------------------------------------------------
#define A_OFF_KV 8192
#define A_OFF_M  57344              // merged (qmask | mask<<1), 512 bytes
#define A_SMEM   57856

__global__ __launch_bounds__(128, 4)
void attn_flash(const int* __restrict__ mask, const int* __restrict__ qmask,
                const float* __restrict__ shiftp, const float* __restrict__ biasp)
{
    extern __shared__ __align__(1024) char sm8[];
    const int tid  = threadIdx.x;
    const int lane = tid & 31;
    const int w    = tid >> 5;
    const int qt = blockIdx.x, h = blockIdx.y, b = blockIdx.z;
    const int lrow = lane & 15, lhi = lane >> 4;
    const int g = lane >> 2, t4 = lane & 3;

    const uint32_t su  = (uint32_t)__cvta_generic_to_shared(sm8);
    const uint32_t uKV = su + A_OFF_KV;
    char* sM8 = sm8 + A_OFF_M;

    const float shiftv = shiftp[0];
    const float biasv  = biasp[0];
    const size_t rowb  = (size_t)b * SEQ;

    for (int i = tid; i < 512; i += 128)
        sM8[i] = (char)(qmask[rowb + i] | (mask[rowb + i] << 1));

    // Q tile (fp16)
#pragma unroll
    for (int j = 0; j < 4; j++) {
        const int slot = j * 128 + tid;
        const int row = slot >> 3, sl = slot & 7;
        CPASYNC16(su + sw128((uint32_t)(row * 128 + sl * 16)),
                  g_Qh + (rowb + qt * 64 + row) * 4096 + h * 64 + sl * 8);
    }
    CPCOMMIT();

    auto ldKV = [&](int buf, int kt) {
        const uint32_t base = uKV + buf * 24576;
#pragma unroll
        for (int t = 0; t < 3; t++) {
            const int colb = (t + 1) * 1024 + h * 64;
#pragma unroll
            for (int j = 0; j < 4; j++) {
                const int slot = j * 128 + tid;
                const int row = slot >> 3, sl = slot & 7;
                CPASYNC16(base + t * 8192 + sw128((uint32_t)(row * 128 + sl * 16)),
                          g_Qh + (rowb + kt * 64 + row) * 4096 + colb + sl * 8);
            }
        }
        CPCOMMIT();
    };

    ldKV(0, 0);
    ldKV(1, 1);

    CPWAIT(2);                  // Q landed
    __syncthreads();

    uint32_t qh[4][4];
#pragma unroll
    for (int ks = 0; ks < 4; ks++) {
        uint32_t off = sw128((uint32_t)((w * 16 + lrow) * 128 + (ks * 2 + lhi) * 16));
        LDSM4(qh[ks][0], qh[ks][1], qh[ks][2], qh[ks][3], su + off);
    }

    char  qmv[2];
    float qgf[2];
#pragma unroll
    for (int hf = 0; hf < 2; hf++) {
        const int qr = qt * 64 + w * 16 + g + hf * 8;
        qmv[hf] = sM8[qr] & 1;
        qgf[hf] = (float)qr;
    }

    float o[8][4];
#pragma unroll
    for (int d = 0; d < 8; d++)
#pragma unroll
        for (int q = 0; q < 4; q++) o[d][q] = 0.f;
    float mx[2] = {-1e30f, -1e30f};
    float sum[2] = {0.f, 0.f};

    for (int kt = 0; kt < 8; kt++) {
        if (kt == 7) { CPWAIT(0); } else { CPWAIT(1); }
        __syncthreads();
        const uint32_t kb = uKV + (kt & 1) * 24576;

        // ---- phase 1: scores for all 64 keys of this chunk ----
        float sv[4][2][2][2];               // [kp][nf][e][hf]
        float cmax[2] = {-1e30f, -1e30f};
#pragma unroll
        for (int kp = 0; kp < 4; kp++) {
            float a1[2][4], a2[2][4];
#pragma unroll
            for (int nf = 0; nf < 2; nf++)
#pragma unroll
                for (int q = 0; q < 4; q++) { a1[nf][q] = 0.f; a2[nf][q] = 0.f; }

#pragma unroll
            for (int ks = 0; ks < 4; ks++) {
                uint32_t k1h[4], k2h[4];
                uint32_t off = sw128((uint32_t)((kp * 16 + lrow) * 128 + (ks * 2 + lhi) * 16));
                LDSM4(k1h[0], k1h[1], k1h[2], k1h[3], kb + off);
                LDSM4(k2h[0], k2h[1], k2h[2], k2h[3], kb + 8192 + off);
#pragma unroll
                for (int nf = 0; nf < 2; nf++) {
                    mma16816(a1[nf], qh[ks], k1h[nf], k1h[2 + nf]);
                    mma16816(a2[nf], qh[ks], k2h[nf], k2h[2 + nf]);
                }
            }

#pragma unroll
            for (int nf = 0; nf < 2; nf++)
#pragma unroll
                for (int e = 0; e < 2; e++) {
                    const int kg = kt * 64 + kp * 16 + nf * 8 + t4 * 2 + e;
                    const char m = sM8[kg];
                    const char km = m & 1;
                    const char mk = m >> 1;
                    const float kgf = (float)kg;
#pragma unroll
                    for (int hf = 0; hf < 2; hf++) {
                        const float v = (qmv[hf] == km) ? a1[nf][hf * 2 + e]
                                                        : a2[nf][hf * 2 + e];
                        const float dd = qgf[hf] - kgf;
                        float s = v * 0.125f - (shiftv * dd * dd + biasv);
                        if (!mk) s = -1e30f;
                        sv[kp][nf][e][hf] = s;
                        cmax[hf] = fmaxf(cmax[hf], s);
                    }
                }
        }

        // ---- phase 2: one softmax update per 64-key chunk ----
#pragma unroll
        for (int hf = 0; hf < 2; hf++) {
            cmax[hf] = fmaxf(cmax[hf], __shfl_xor_sync(0xffffffffu, cmax[hf], 1));
            cmax[hf] = fmaxf(cmax[hf], __shfl_xor_sync(0xffffffffu, cmax[hf], 2));
        }
        float corr[2];
#pragma unroll
        for (int hf = 0; hf < 2; hf++) {
            const float nm = fmaxf(mx[hf], cmax[hf]);
            corr[hf] = __expf(mx[hf] - nm);
            mx[hf] = nm;
            sum[hf] *= corr[hf];
        }
#pragma unroll
        for (int d = 0; d < 8; d++) {
            o[d][0] *= corr[0]; o[d][1] *= corr[0];
            o[d][2] *= corr[1]; o[d][3] *= corr[1];
        }

        // ---- phase 3: exp + pack P fragments (fp16, single-term) ----
        uint32_t pH[4][4];
#pragma unroll
        for (int kp = 0; kp < 4; kp++)
#pragma unroll
            for (int nf = 0; nf < 2; nf++)
#pragma unroll
                for (int hf = 0; hf < 2; hf++) {
                    const float p0 = __expf(sv[kp][nf][0][hf] - mx[hf]);
                    const float p1 = __expf(sv[kp][nf][1][hf] - mx[hf]);
                    sum[hf] += p0 + p1;
                    pH[kp][nf * 2 + hf] = pkh2(p0, p1);
                }

        // ---- phase 4: P @ Vh over the 64-key chunk ----
        const int quad = lane >> 3, r = lane & 7;
#pragma unroll
        for (int dblk = 0; dblk < 4; dblk++) {
#pragma unroll
            for (int kp = 0; kp < 4; kp++) {
                uint32_t vh[4];
                uint32_t boff = sw128((uint32_t)((kp * 16 + (quad & 1) * 8 + r) * 128
                                                 + dblk * 32 + (quad >> 1) * 16));
                LDSM4T(vh[0], vh[1], vh[2], vh[3], kb + 16384 + boff);
#pragma unroll
                for (int nf = 0; nf < 2; nf++)
                    mma16816(o[dblk * 2 + nf], pH[kp], vh[nf * 2], vh[nf * 2 + 1]);
            }
        }
        __syncthreads();
        if (kt + 2 < 8) ldKV(kt & 1, kt + 2);
    }

    // finalize: normalize, write fp16 att into g_Ah
    float inv[2];
#pragma unroll
    for (int hf = 0; hf < 2; hf++) {
        float s = sum[hf];
        s += __shfl_xor_sync(0xffffffffu, s, 1);
        s += __shfl_xor_sync(0xffffffffu, s, 2);
        inv[hf] = 1.0f / s;
    }
#pragma unroll
    for (int d = 0; d < 8; d++) {
        const int col = h * 64 + (d >> 1) * 16 + (d & 1) * 8 + t4 * 2;
#pragma unroll
        for (int hf = 0; hf < 2; hf++) {
            const size_t row = rowb + qt * 64 + w * 16 + g + hf * 8;
            const float v0 = o[d][hf * 2 + 0] * inv[hf];
            const float v1 = o[d][hf * 2 + 1] * inv[hf];
            *(uint32_t*)(g_Ah + row * DMODEL + col) = pkh2(v0, v1);
        }
    }
}

// ---------------------------------------------------------------------------
extern "C" void kernel_launch(void* const* d_in, const int* in_sizes, int n_in,
                              void* d_out, int out_size)
{
    const float* x     = (const float*)d_in[0];
    const int*   mask  = (const int*)  d_in[1];
    const int*   qmask = (const int*)  d_in[2];
    const float* Wqkv  = (const float*)d_in[3];
    const float* fc_w  = (const float*)d_in[4];
    const float* fc_b  = (const float*)d_in[5];
    const float* shift = (const float*)d_in[6];
    const float* bias  = (const float*)d_in[7];
    float* out = (float*)d_out;

    __half *qh, *ah, *bh, *wh;
    cudaGetSymbolAddress((void**)&qh, g_Qh);
    cudaGetSymbolAddress((void**)&ah, g_Ah);
    cudaGetSymbolAddress((void**)&bh, g_Bh);
    cudaGetSymbolAddress((void**)&wh, g_Wh);

    cudaFuncSetAttribute(gemm_hmma<true>,  cudaFuncAttributeMaxDynamicSharedMemorySize, 2 * G_STAGE);
    cudaFuncSetAttribute(gemm_hmma<false>, cudaFuncAttributeMaxDynamicSharedMemorySize, 2 * G_STAGE);
    cudaFuncSetAttribute(attn_flash, cudaFuncAttributeMaxDynamicSharedMemorySize, A_SMEM);

    // 1) fp16 conversions: x -> Ah, Wqkv -> Bh, fc_w -> Wh
    {
        const int total = 2 * N_A4 + N_W4;
        cvt3<<<(total + 255) / 256, 256>>>((const float4*)x, (const float4*)Wqkv,
                                           (const float4*)fc_w);
    }

    // 2) qkv = x @ Wqkv^T, fp16 epilogue
    {
        dim3 grid(4 * DMODEL / 128, MROWS / 128);   // (32, 32)
        gemm_hmma<true><<<grid, 256, 2 * G_STAGE>>>(ah, bh, nullptr, nullptr,
                                                    qh, 4 * DMODEL, DMODEL);
    }

    // 3) flash attention, writes fp16 att into g_Ah
    {
        dim3 grid(SEQ / 64, NHEAD, BATCH);          // (8, 16, 8)
        attn_flash<<<grid, 128, A_SMEM>>>(mask, qmask, shift, bias);
    }

    // 4) out = att @ fc_w^T + fc_b (fp32 epilogue)
    {
        dim3 grid(DMODEL / 128, MROWS / 128);       // (8, 32)
        gemm_hmma<false><<<grid, 256, 2 * G_STAGE>>>(ah, wh, fc_b, out,
                                                     nullptr, DMODEL, DMODEL);
    }
}